// round 3
// baseline (speedup 1.0000x reference)
#include <cuda_runtime.h>
#include <cuda_bf16.h>
#include <math.h>

// Problem constants
#define S    2048
#define HID  1024
#define NH   16
#define NKV  4
#define HD   64

// ---------------- scratch (device globals; no allocations allowed) ----------
__device__ float g_Q[S * NH * HD];     // 8 MB   [s, h*64+d]
__device__ float g_K[S * NKV * HD];    // 2 MB   [s, kh*64+d]
__device__ float g_V[S * NKV * HD];    // 2 MB
__device__ float g_attn[S * NH * HD];  // 8 MB   [s, h*64+d]

// ---------------- SGEMM: C[M,N] = A[M,K] @ B[K,N], all row-major ------------
// 128x128 tile, BK=8, 256 threads, 8x8 per thread. All dims divisible.
#define BM 128
#define BN 128
#define BK 8
#define TM 8
#define TN 8

__global__ __launch_bounds__(256) void sgemm_kernel(
    const float* __restrict__ A, const float* __restrict__ B,
    float* __restrict__ C, int M, int N, int K)
{
    __shared__ float As[BK][BM];
    __shared__ float Bs[BK][BN];

    const int bx = blockIdx.x;   // N tile
    const int by = blockIdx.y;   // M tile
    const int tid = threadIdx.x; // 0..255
    const int tx = tid & 15;     // 0..15 (N dir)
    const int ty = tid >> 4;     // 0..15 (M dir)

    const int aRow = tid >> 1;          // 0..127
    const int aCol = (tid & 1) * 4;     // 0 or 4
    const int bRow = tid >> 5;          // 0..7
    const int bCol = (tid & 31) * 4;    // 0..124

    const float* Ab = A + (size_t)(by * BM) * K;
    const float* Bb = B + bx * BN;

    float acc[TM][TN];
    #pragma unroll
    for (int i = 0; i < TM; i++)
        #pragma unroll
        for (int j = 0; j < TN; j++) acc[i][j] = 0.f;

    for (int k0 = 0; k0 < K; k0 += BK) {
        float4 av = *(const float4*)(Ab + (size_t)aRow * K + k0 + aCol);
        As[aCol + 0][aRow] = av.x;
        As[aCol + 1][aRow] = av.y;
        As[aCol + 2][aRow] = av.z;
        As[aCol + 3][aRow] = av.w;
        *(float4*)(&Bs[bRow][bCol]) =
            *(const float4*)(Bb + (size_t)(k0 + bRow) * N + bCol);
        __syncthreads();

        #pragma unroll
        for (int kk = 0; kk < BK; kk++) {
            float a[TM], b[TN];
            #pragma unroll
            for (int i = 0; i < TM; i++) a[i] = As[kk][ty * TM + i];
            #pragma unroll
            for (int j = 0; j < TN; j++) b[j] = Bs[kk][tx * TN + j];
            #pragma unroll
            for (int i = 0; i < TM; i++)
                #pragma unroll
                for (int j = 0; j < TN; j++) acc[i][j] += a[i] * b[j];
        }
        __syncthreads();
    }

    float* Cb = C + (size_t)(by * BM + ty * TM) * N + bx * BN + tx * TN;
    #pragma unroll
    for (int i = 0; i < TM; i++) {
        #pragma unroll
        for (int j = 0; j < TN; j += 4) {
            float4 v = make_float4(acc[i][j], acc[i][j+1], acc[i][j+2], acc[i][j+3]);
            *(float4*)(Cb + (size_t)i * N + j) = v;
        }
    }
}

// ---------------- RoPE (in place) -------------------------------------------
// X: [S, nHeads*64]. Pair p (0..31) rotates (2p, 2p+1) within each head by
// angle = s * theta^{-(p mod 16)/16}.
// Derivation: inv_freq[i] = theta^{-i/32}; emb = concat([freqs, freqs]);
// cos table entry p = cos(emb[2p]) -> freqs[2p] (p<16) or freqs[2p-32] (p>=16),
// i.e. exponent 2p/32 = p/16 resp. (2p-32)/32 = (p-16)/16 -> (p mod 16)/16.
__global__ void rope_kernel(float* __restrict__ X, int nHeads)
{
    int idx = blockIdx.x * blockDim.x + threadIdx.x;
    int total = S * nHeads * 32;
    if (idx >= total) return;
    int p = idx & 31;
    int h = (idx >> 5) % nHeads;
    int s = idx / (32 * nHeads);

    float e = (float)(p & 15) / 16.0f;
    float inv = 1.0f / powf(10000.0f, e);
    float ang = (float)s * inv;
    float sn, cs;
    sincosf(ang, &sn, &cs);

    float* base = X + (size_t)s * nHeads * HD + h * HD;
    float xe = base[2 * p];
    float xo = base[2 * p + 1];
    base[2 * p]     = xe * cs - xo * sn;
    base[2 * p + 1] = xe * sn + xo * cs;
}

// ---------------- Flash attention (causal, GQA 4:1) -------------------------
// One block = 128 query rows of one head; 1 thread = 1 row.
// q[64] and acc[64] in registers; K/V tiles (64x64) in smem (broadcast reads).
#define BMA 128
#define BKV 64

__global__ __launch_bounds__(BMA) void attn_kernel(
    const float* __restrict__ Q, const float* __restrict__ Kt,
    const float* __restrict__ Vt, float* __restrict__ O)
{
    __shared__ float Ks[BKV][HD];
    __shared__ float Vs[BKV][HD];

    const int h   = blockIdx.y;
    const int qb  = gridDim.x - 1 - blockIdx.x;  // heavy tiles first
    const int r   = qb * BMA + threadIdx.x;
    const int kvh = h >> 2;
    const float scale = 0.125f;                  // 1/sqrt(64)

    float q[HD];
    const float* qp = Q + (size_t)r * (NH * HD) + h * HD;
    #pragma unroll
    for (int d = 0; d < HD; d++) q[d] = qp[d] * scale;

    float m = -1e30f, l = 0.f;
    float acc[HD];
    #pragma unroll
    for (int d = 0; d < HD; d++) acc[d] = 0.f;

    const int ntiles = (qb * BMA + BMA) / BKV;   // 2*qb + 2
    const int tid = threadIdx.x;

    for (int t = 0; t < ntiles; t++) {
        const int kv0 = t * BKV;
        __syncthreads();
        // cooperative tile load: BKV*16 float4 per tile
        for (int i = tid; i < BKV * (HD / 4); i += BMA) {
            int row = i >> 4;
            int c4  = (i & 15) * 4;
            const size_t src = (size_t)(kv0 + row) * (NKV * HD) + kvh * HD + c4;
            *(float4*)&Ks[row][c4] = *(const float4*)(Kt + src);
            *(float4*)&Vs[row][c4] = *(const float4*)(Vt + src);
        }
        __syncthreads();

        int jmax = r - kv0 + 1;
        if (jmax > BKV) jmax = BKV;
        for (int j = 0; j < jmax; j++) {
            float sc = 0.f;
            #pragma unroll
            for (int d = 0; d < HD; d++) sc += q[d] * Ks[j][d];
            if (sc > m) {
                float f = __expf(m - sc);
                l *= f;
                #pragma unroll
                for (int d = 0; d < HD; d++) acc[d] *= f;
                m = sc;
            }
            float p = __expf(sc - m);
            l += p;
            #pragma unroll
            for (int d = 0; d < HD; d++) acc[d] += p * Vs[j][d];
        }
    }

    float invl = 1.0f / l;
    float* op = O + (size_t)r * (NH * HD) + h * HD;
    #pragma unroll
    for (int d = 0; d < HD; d++) op[d] = acc[d] * invl;
}

// ---------------- launch ----------------------------------------------------
extern "C" void kernel_launch(void* const* d_in, const int* in_sizes, int n_in,
                              void* d_out, int out_size)
{
    const float* X  = (const float*)d_in[0];
    const float* Wq = (const float*)d_in[1];
    const float* Wk = (const float*)d_in[2];
    const float* Wv = (const float*)d_in[3];
    const float* Wo = (const float*)d_in[4];
    float* out = (float*)d_out;

    float *pQ, *pK, *pV, *pA;
    cudaGetSymbolAddress((void**)&pQ, g_Q);
    cudaGetSymbolAddress((void**)&pK, g_K);
    cudaGetSymbolAddress((void**)&pV, g_V);
    cudaGetSymbolAddress((void**)&pA, g_attn);

    // QKV projections
    sgemm_kernel<<<dim3((NH * HD) / BN, S / BM), 256>>>(X, Wq, pQ, S, NH * HD, HID);
    sgemm_kernel<<<dim3((NKV * HD) / BN, S / BM), 256>>>(X, Wk, pK, S, NKV * HD, HID);
    sgemm_kernel<<<dim3((NKV * HD) / BN, S / BM), 256>>>(X, Wv, pV, S, NKV * HD, HID);

    // RoPE on Q and K
    {
        int totQ = S * NH * 32;
        rope_kernel<<<(totQ + 255) / 256, 256>>>(pQ, NH);
        int totK = S * NKV * 32;
        rope_kernel<<<(totK + 255) / 256, 256>>>(pK, NKV);
    }

    // Attention
    attn_kernel<<<dim3(S / BMA, NH), BMA>>>(pQ, pK, pV, pA);

    // Output projection
    sgemm_kernel<<<dim3(HID / BN, S / BM), 256>>>(pA, Wo, out, S, HID, HID);
}

// round 5
// speedup vs baseline: 1.0747x; 1.0747x over previous
#include <cuda_runtime.h>
#include <cuda_bf16.h>
#include <math.h>
#include <stdint.h>

// Problem constants
#define S    2048
#define HID  1024
#define NH   16
#define NKV  4
#define HD   64

// ---------------- scratch (device globals; no allocations allowed) ----------
__device__ float g_Q[S * NH * HD];
__device__ float g_K[S * NKV * HD];
__device__ float g_V[S * NKV * HD];
__device__ float g_attn[S * NH * HD];

// ---------------- helpers ----------------------------------------------------
__device__ __forceinline__ float t13(float x) {          // tf32 "hi" part
    return __uint_as_float(__float_as_uint(x) & 0xFFFFE000u);
}

// m16n8k8 tf32 mma, D += A*B (acc in d)
__device__ __forceinline__ void mma8(float* d, const uint32_t* a, const uint32_t* b) {
    asm volatile(
        "mma.sync.aligned.m16n8k8.row.col.f32.tf32.tf32.f32 "
        "{%0,%1,%2,%3}, {%4,%5,%6,%7}, {%8,%9}, {%0,%1,%2,%3};"
        : "+f"(d[0]), "+f"(d[1]), "+f"(d[2]), "+f"(d[3])
        : "r"(a[0]), "r"(a[1]), "r"(a[2]), "r"(a[3]), "r"(b[0]), "r"(b[1]));
}

// ================= tensor-core tf32 GEMM (3xTF32 hi/lo) ======================
// C[M,N] = A[M,1024] @ B[1024,N], row-major. Block tile BM=128 x BN, BK=32.
// 256 threads = 8 warps: 4 (M) x 2 (N). Warp tile 32 x (BN/2).
// SMEM holds A and B chunks pre-shuffled into mma fragment order:
//   Afrag[k8][mtile][lane][4]  (a0..a3 of m16k8 tile)  -> lds.128 per tile
//   Bfrag[k8][ntile][lane][2]  (b0,b1 of k8n8 tile)    -> lds.64  per tile
template <int BN>
__global__ __launch_bounds__(256, 1) void gemm_mma_kernel(
    const float* __restrict__ A, const float* __restrict__ B,
    float* __restrict__ C, int ldb, int ldc, int do_rope)
{
    constexpr int NTILES = BN / 8;       // total n8 tiles in block
    constexpr int NTW    = NTILES / 2;   // n8 tiles per warp

    __shared__ float Afrag[4 * 8 * 32 * 4];       // 16 KB
    __shared__ float Bfrag[4 * NTILES * 32 * 2];  // 16/8 KB

    const int tid  = threadIdx.x;
    const int wid  = tid >> 5;
    const int lane = tid & 31;
    const int wm   = wid & 3;      // 0..3 (M)
    const int wn   = wid >> 2;     // 0..1 (N)
    const int m0   = blockIdx.y * 128;
    const int n0   = blockIdx.x * BN;

    float acc[2][NTW][4];
    #pragma unroll
    for (int i = 0; i < 2; i++)
        #pragma unroll
        for (int j = 0; j < NTW; j++)
            #pragma unroll
            for (int v = 0; v < 4; v++) acc[i][j][v] = 0.f;

    for (int ch = 0; ch < 32; ch++) {
        const int kc0 = ch * 32;

        // ---- stage A (128 rows x 32 k) into fragment order ----
        #pragma unroll
        for (int u = tid; u < 128 * 8; u += 256) {
            int row = u >> 3;
            int q   = u & 7;
            float4 av = *(const float4*)(A + (size_t)(m0 + row) * HID + kc0 + q * 4);
            float vals[4] = {av.x, av.y, av.z, av.w};
            int mt  = row >> 4;
            int r16 = row & 15;
            #pragma unroll
            for (int f = 0; f < 4; f++) {
                int k   = q * 4 + f;
                int k8  = k >> 3;
                int kk  = k & 7;
                int ln  = ((r16 & 7) << 2) | (k & 3);
                int vec = (r16 >> 3) | ((kk >> 2) << 1);
                Afrag[((((k8 << 3) + mt) << 5) + ln) * 4 + vec] = vals[f];
            }
        }
        // ---- stage B (32 k x BN cols) into fragment order ----
        #pragma unroll
        for (int u = tid; u < 32 * (BN / 4); u += 256) {
            int kkr = u / (BN / 4);
            int n4  = (u % (BN / 4)) * 4;
            float4 bv = *(const float4*)(B + (size_t)(kc0 + kkr) * ldb + n0 + n4);
            float vals[4] = {bv.x, bv.y, bv.z, bv.w};
            int k8  = kkr >> 3;
            int vec = (kkr >> 2) & 1;
            #pragma unroll
            for (int f = 0; f < 4; f++) {
                int n  = n4 + f;
                int nt = n >> 3;
                int ln = ((n & 7) << 2) | (kkr & 3);
                Bfrag[(((k8 * NTILES + nt) << 5) + ln) * 2 + vec] = vals[f];
            }
        }
        __syncthreads();

        // ---- compute: 4 k8-steps x 3 precision passes ----
        #pragma unroll
        for (int k8 = 0; k8 < 4; k8++) {
            float4 araw[2];
            #pragma unroll
            for (int mt = 0; mt < 2; mt++)
                araw[mt] = *(const float4*)
                    &Afrag[((((k8 << 3) + wm * 2 + mt) << 5) + lane) * 4];
            uint32_t ah[2][4], al[2][4];
            #pragma unroll
            for (int mt = 0; mt < 2; mt++) {
                const float* ap = (const float*)&araw[mt];
                #pragma unroll
                for (int v = 0; v < 4; v++) {
                    float h = t13(ap[v]);
                    ah[mt][v] = __float_as_uint(h);
                    al[mt][v] = __float_as_uint(ap[v] - h);
                }
            }
            uint32_t bh[NTW][2], bl[NTW][2];
            #pragma unroll
            for (int nt = 0; nt < NTW; nt++) {
                float2 braw = *(const float2*)
                    &Bfrag[(((k8 * NTILES + wn * NTW + nt) << 5) + lane) * 2];
                float h0 = t13(braw.x), h1 = t13(braw.y);
                bh[nt][0] = __float_as_uint(h0);
                bh[nt][1] = __float_as_uint(h1);
                bl[nt][0] = __float_as_uint(braw.x - h0);
                bl[nt][1] = __float_as_uint(braw.y - h1);
            }
            #pragma unroll
            for (int mt = 0; mt < 2; mt++)
                #pragma unroll
                for (int nt = 0; nt < NTW; nt++) {
                    mma8(acc[mt][nt], ah[mt], bh[nt]);
                    mma8(acc[mt][nt], ah[mt], bl[nt]);
                    mma8(acc[mt][nt], al[mt], bh[nt]);
                }
        }
        __syncthreads();
    }

    // ---- epilogue: optional fused RoPE, then store ----
    const float L2T_16 = 13.287712379549449f / 16.0f;  // log2(10000)/16
    #pragma unroll
    for (int mt = 0; mt < 2; mt++) {
        int rbase = m0 + wm * 32 + mt * 16 + (lane >> 2);
        #pragma unroll
        for (int nt = 0; nt < NTW; nt++) {
            int c = n0 + (wn * NTW + nt) * 8 + (lane & 3) * 2;
            float inv = 0.f;
            if (do_rope) {
                int fidx = (c >> 1) & 15;
                inv = exp2f(-(float)fidx * L2T_16);
            }
            #pragma unroll
            for (int half = 0; half < 2; half++) {
                int row = rbase + half * 8;
                float e = acc[mt][nt][half * 2];
                float o = acc[mt][nt][half * 2 + 1];
                if (do_rope) {
                    float sn, cs;
                    sincosf((float)row * inv, &sn, &cs);
                    float re = e * cs - o * sn;
                    float ro = e * sn + o * cs;
                    e = re; o = ro;
                }
                *(float2*)(C + (size_t)row * ldc + c) = make_float2(e, o);
            }
        }
    }
}

// ---------------- Flash attention (causal, GQA 4:1) -------------------------
#define BMA 128
#define BKV 64

__global__ __launch_bounds__(BMA) void attn_kernel(
    const float* __restrict__ Q, const float* __restrict__ Kt,
    const float* __restrict__ Vt, float* __restrict__ O)
{
    __shared__ float Ks[BKV][HD];
    __shared__ float Vs[BKV][HD];

    const int h   = blockIdx.y;
    const int qb  = gridDim.x - 1 - blockIdx.x;  // heavy tiles first
    const int r   = qb * BMA + threadIdx.x;
    const int kvh = h >> 2;
    const float scale = 0.125f;

    float q[HD];
    const float* qp = Q + (size_t)r * (NH * HD) + h * HD;
    #pragma unroll
    for (int d = 0; d < HD; d++) q[d] = qp[d] * scale;

    float m = -1e30f, l = 0.f;
    float acc[HD];
    #pragma unroll
    for (int d = 0; d < HD; d++) acc[d] = 0.f;

    const int ntiles = (qb * BMA + BMA) / BKV;
    const int tid = threadIdx.x;

    for (int t = 0; t < ntiles; t++) {
        const int kv0 = t * BKV;
        __syncthreads();
        for (int i = tid; i < BKV * (HD / 4); i += BMA) {
            int row = i >> 4;
            int c4  = (i & 15) * 4;
            const size_t src = (size_t)(kv0 + row) * (NKV * HD) + kvh * HD + c4;
            *(float4*)&Ks[row][c4] = *(const float4*)(Kt + src);
            *(float4*)&Vs[row][c4] = *(const float4*)(Vt + src);
        }
        __syncthreads();

        int jmax = r - kv0 + 1;
        if (jmax > BKV) jmax = BKV;
        for (int j = 0; j < jmax; j++) {
            float s0 = 0.f, s1 = 0.f, s2 = 0.f, s3 = 0.f;
            #pragma unroll
            for (int d = 0; d < HD; d += 4) {
                s0 += q[d]     * Ks[j][d];
                s1 += q[d + 1] * Ks[j][d + 1];
                s2 += q[d + 2] * Ks[j][d + 2];
                s3 += q[d + 3] * Ks[j][d + 3];
            }
            float sc = (s0 + s1) + (s2 + s3);
            if (sc > m) {
                float f = __expf(m - sc);
                l *= f;
                #pragma unroll
                for (int d = 0; d < HD; d++) acc[d] *= f;
                m = sc;
            }
            float p = __expf(sc - m);
            l += p;
            #pragma unroll
            for (int d = 0; d < HD; d++) acc[d] += p * Vs[j][d];
        }
    }

    float invl = 1.0f / l;
    float* op = O + (size_t)r * (NH * HD) + h * HD;
    #pragma unroll
    for (int d = 0; d < HD; d++) op[d] = acc[d] * invl;
}

// ---------------- launch ----------------------------------------------------
extern "C" void kernel_launch(void* const* d_in, const int* in_sizes, int n_in,
                              void* d_out, int out_size)
{
    const float* X  = (const float*)d_in[0];
    const float* Wq = (const float*)d_in[1];
    const float* Wk = (const float*)d_in[2];
    const float* Wv = (const float*)d_in[3];
    const float* Wo = (const float*)d_in[4];
    float* out = (float*)d_out;

    float *pQ, *pK, *pV, *pA;
    cudaGetSymbolAddress((void**)&pQ, g_Q);
    cudaGetSymbolAddress((void**)&pK, g_K);
    cudaGetSymbolAddress((void**)&pV, g_V);
    cudaGetSymbolAddress((void**)&pA, g_attn);

    // QKV projections (RoPE fused into Q and K epilogues)
    gemm_mma_kernel<128><<<dim3(8, 16), 256>>>(X, Wq, pQ, NH * HD, NH * HD, 1);
    gemm_mma_kernel<64><<<dim3(4, 16), 256>>>(X, Wk, pK, NKV * HD, NKV * HD, 1);
    gemm_mma_kernel<64><<<dim3(4, 16), 256>>>(X, Wv, pV, NKV * HD, NKV * HD, 0);

    // Attention
    attn_kernel<<<dim3(S / BMA, NH), BMA>>>(pQ, pK, pV, pA);

    // Output projection
    gemm_mma_kernel<128><<<dim3(8, 16), 256>>>(pA, Wo, out, HID, HID, 0);
}

// round 6
// speedup vs baseline: 1.5027x; 1.3983x over previous
#include <cuda_runtime.h>
#include <cuda_bf16.h>
#include <math.h>
#include <stdint.h>

// Problem constants
#define S    2048
#define HID  1024
#define NH   16
#define NKV  4
#define HD   64

// ---------------- scratch (device globals; no allocations allowed) ----------
__device__ float g_Q[S * NH * HD];
__device__ float g_K[S * NKV * HD];
__device__ float g_V[S * NKV * HD];
__device__ float g_attn[S * NH * HD];

// ---------------- helpers ----------------------------------------------------
__device__ __forceinline__ float t13(float x) {          // tf32 "hi" part
    return __uint_as_float(__float_as_uint(x) & 0xFFFFE000u);
}
__device__ __forceinline__ uint32_t t13u(float x) {
    return __float_as_uint(x) & 0xFFFFE000u;
}

// m16n8k8 tf32 mma, D += A*B
__device__ __forceinline__ void mma8(float* d, const uint32_t* a, const uint32_t* b) {
    asm volatile(
        "mma.sync.aligned.m16n8k8.row.col.f32.tf32.tf32.f32 "
        "{%0,%1,%2,%3}, {%4,%5,%6,%7}, {%8,%9}, {%0,%1,%2,%3};"
        : "+f"(d[0]), "+f"(d[1]), "+f"(d[2]), "+f"(d[3])
        : "r"(a[0]), "r"(a[1]), "r"(a[2]), "r"(a[3]), "r"(b[0]), "r"(b[1]));
}

// ================= tensor-core tf32 GEMM (3xTF32, double-buffered) ===========
// C[M,N] = A[M,1024] @ B[1024,N]. Block tile 128 x 128, BK=32.
// 256 threads = 8 warps (4 M x 2 N). One launch can cover up to 3 (B,C) regions
// along blockIdx.x (for merged QKV). Dynamic smem: 2 x (A 4096 + B 4096) floats.
#define GEMM_SMEM (2 * 8192 * 4)

__device__ __forceinline__ void gemm_compute(
    const float* __restrict__ Af, const float* __restrict__ Bf,
    int wm, int wn, int lane, float acc[2][8][4])
{
    #pragma unroll
    for (int k8 = 0; k8 < 4; k8++) {
        uint32_t ah[2][4], al[2][4];
        #pragma unroll
        for (int mt = 0; mt < 2; mt++) {
            float4 araw = *(const float4*)
                &Af[((((k8 << 3) + wm * 2 + mt) << 5) + lane) * 4];
            const float* ap = (const float*)&araw;
            #pragma unroll
            for (int v = 0; v < 4; v++) {
                float h = t13(ap[v]);
                ah[mt][v] = __float_as_uint(h);
                al[mt][v] = __float_as_uint(ap[v] - h);
            }
        }
        #pragma unroll
        for (int nt = 0; nt < 8; nt++) {
            float2 braw = *(const float2*)
                &Bf[(((k8 * 16 + wn * 8 + nt) << 5) + lane) * 2];
            uint32_t bh[2], bl[2];
            float h0 = t13(braw.x), h1 = t13(braw.y);
            bh[0] = __float_as_uint(h0);
            bh[1] = __float_as_uint(h1);
            bl[0] = __float_as_uint(braw.x - h0);
            bl[1] = __float_as_uint(braw.y - h1);
            #pragma unroll
            for (int mt = 0; mt < 2; mt++) {
                mma8(acc[mt][nt], ah[mt], bh);
                mma8(acc[mt][nt], ah[mt], bl);
                mma8(acc[mt][nt], al[mt], bh);
            }
        }
    }
}

__global__ __launch_bounds__(256, 2) void gemm_mma_kernel(
    const float* __restrict__ A,
    const float* __restrict__ B0, float* __restrict__ C0, int ld0, int rope0, int nx0,
    const float* __restrict__ B1, float* __restrict__ C1, int ld1, int rope1, int nx1,
    const float* __restrict__ B2, float* __restrict__ C2, int ld2, int rope2)
{
    extern __shared__ float sm[];
    const int tid  = threadIdx.x;
    const int wid  = tid >> 5;
    const int lane = tid & 31;
    const int wm   = wid & 3;
    const int wn   = wid >> 2;
    const int m0   = blockIdx.y * 128;

    const float* B; float* C; int ld, rope, n0;
    {
        int bx = blockIdx.x;
        if (bx < nx0)            { B = B0; C = C0; ld = ld0; rope = rope0; n0 = bx * 128; }
        else if (bx < nx0 + nx1) { B = B1; C = C1; ld = ld1; rope = rope1; n0 = (bx - nx0) * 128; }
        else                     { B = B2; C = C2; ld = ld2; rope = rope2; n0 = (bx - nx0 - nx1) * 128; }
    }

    float acc[2][8][4];
    #pragma unroll
    for (int i = 0; i < 2; i++)
        #pragma unroll
        for (int j = 0; j < 8; j++)
            #pragma unroll
            for (int v = 0; v < 4; v++) acc[i][j][v] = 0.f;

    float4 ar[4], br[4];

    // ---- load chunk regs ----
    auto load_regs = [&](int ch) {
        const int kc0 = ch * 32;
        #pragma unroll
        for (int i = 0; i < 4; i++) {
            int u = tid + i * 256;
            int row = u >> 3, q = u & 7;
            ar[i] = *(const float4*)(A + (size_t)(m0 + row) * HID + kc0 + q * 4);
        }
        #pragma unroll
        for (int i = 0; i < 4; i++) {
            int u = tid + i * 256;
            int kkr = u >> 5, n4 = (u & 31) << 2;
            br[i] = *(const float4*)(B + (size_t)(kc0 + kkr) * ld + n0 + n4);
        }
    };
    // ---- scatter regs into fragment-ordered smem buffer ----
    auto scatter = [&](int buf) {
        float* Af = sm + buf * 4096;
        float* Bf = sm + 8192 + buf * 4096;
        #pragma unroll
        for (int i = 0; i < 4; i++) {
            int u = tid + i * 256;
            int row = u >> 3, q = u & 7;
            int mt = row >> 4, r16 = row & 15;
            const float* v = (const float*)&ar[i];
            #pragma unroll
            for (int f = 0; f < 4; f++) {
                int k = q * 4 + f, k8 = k >> 3, kk = k & 7;
                int ln  = ((r16 & 7) << 2) | (k & 3);
                int vec = (r16 >> 3) | ((kk >> 2) << 1);
                Af[((((k8 << 3) + mt) << 5) + ln) * 4 + vec] = v[f];
            }
        }
        #pragma unroll
        for (int i = 0; i < 4; i++) {
            int u = tid + i * 256;
            int kkr = u >> 5, n4 = (u & 31) << 2;
            int k8 = kkr >> 3, vec = (kkr >> 2) & 1;
            const float* v = (const float*)&br[i];
            #pragma unroll
            for (int f = 0; f < 4; f++) {
                int n = n4 + f, nt = n >> 3;
                int ln = ((n & 7) << 2) | (kkr & 3);
                Bf[(((k8 * 16 + nt) << 5) + ln) * 2 + vec] = v[f];
            }
        }
    };

    load_regs(0);
    scatter(0);
    __syncthreads();
    for (int ch = 0; ch < 32; ch++) {
        if (ch < 31) load_regs(ch + 1);
        gemm_compute(sm + (ch & 1) * 4096, sm + 8192 + (ch & 1) * 4096,
                     wm, wn, lane, acc);
        if (ch < 31) scatter((ch + 1) & 1);
        __syncthreads();
    }

    // ---- epilogue: optional fused RoPE, then store ----
    const float L2T_16 = 13.287712379549449f / 16.0f;  // log2(10000)/16
    #pragma unroll
    for (int mt = 0; mt < 2; mt++) {
        int rbase = m0 + wm * 32 + mt * 16 + (lane >> 2);
        #pragma unroll
        for (int nt = 0; nt < 8; nt++) {
            int c = n0 + (wn * 8 + nt) * 8 + (lane & 3) * 2;
            float inv = 0.f;
            if (rope) {
                int fidx = (c >> 1) & 15;
                inv = exp2f(-(float)fidx * L2T_16);
            }
            #pragma unroll
            for (int half = 0; half < 2; half++) {
                int row = rbase + half * 8;
                float e = acc[mt][nt][half * 2];
                float o = acc[mt][nt][half * 2 + 1];
                if (rope) {
                    float sn, cs;
                    sincosf((float)row * inv, &sn, &cs);
                    float re = e * cs - o * sn;
                    float ro = e * sn + o * cs;
                    e = re; o = ro;
                }
                *(float2*)(C + (size_t)row * ld + c) = make_float2(e, o);
            }
        }
    }
}

// ================= MMA flash attention (causal, GQA 4:1) =====================
// Block = 128 threads (4 warps) = 64 q rows of one head. KV tiles of 64.
// S = Q K^T via m16n8k8 tf32 (3-pass), O += P V (P trunc-tf32, V hi/lo 2-pass).
// Dynamic smem (floats): Khi[4096] Klo[4096] Vhi[4096] Vlo[4096] Ps[4][16*68]
#define ATT_SMEM ((16384 + 4 * 1088) * 4)

__global__ __launch_bounds__(128) void attn_mma_kernel(
    const float* __restrict__ Q, const float* __restrict__ K,
    const float* __restrict__ V, float* __restrict__ O)
{
    extern __shared__ float sm[];
    float* Khi = sm;
    float* Klo = sm + 4096;
    float* Vhi = sm + 8192;
    float* Vlo = sm + 12288;

    const int tid  = threadIdx.x;
    const int wid  = tid >> 5;
    const int lane = tid & 31;
    float* Ps = sm + 16384 + wid * 1088;   // 16 x 68 per warp

    const int h   = blockIdx.y;
    const int qt  = gridDim.x - 1 - blockIdx.x;  // heavy tiles first
    const int q0  = qt * 64;
    const int kvh = h >> 2;

    // ---- Q fragments (hi/lo), scaled by 1/8 ----
    const int r0 = q0 + wid * 16 + (lane >> 2);
    const int r1 = r0 + 8;
    const int c0 = lane & 3;
    uint32_t qh[8][4], ql[8][4];
    {
        const float* Qb = Q + (size_t)h * HD;
        #pragma unroll
        for (int k8 = 0; k8 < 8; k8++) {
            float v0 = Qb[(size_t)r0 * (NH * HD) + k8 * 8 + c0]     * 0.125f;
            float v1 = Qb[(size_t)r1 * (NH * HD) + k8 * 8 + c0]     * 0.125f;
            float v2 = Qb[(size_t)r0 * (NH * HD) + k8 * 8 + c0 + 4] * 0.125f;
            float v3 = Qb[(size_t)r1 * (NH * HD) + k8 * 8 + c0 + 4] * 0.125f;
            float h0 = t13(v0), h1 = t13(v1), h2 = t13(v2), h3 = t13(v3);
            qh[k8][0] = __float_as_uint(h0); ql[k8][0] = __float_as_uint(v0 - h0);
            qh[k8][1] = __float_as_uint(h1); ql[k8][1] = __float_as_uint(v1 - h1);
            qh[k8][2] = __float_as_uint(h2); ql[k8][2] = __float_as_uint(v2 - h2);
            qh[k8][3] = __float_as_uint(h3); ql[k8][3] = __float_as_uint(v3 - h3);
        }
    }

    float m0 = -1e30f, m1 = -1e30f, l0 = 0.f, l1 = 0.f;
    float o[8][4];
    #pragma unroll
    for (int nt = 0; nt < 8; nt++)
        #pragma unroll
        for (int v = 0; v < 4; v++) o[nt][v] = 0.f;

    for (int t = 0; t <= qt; t++) {
        const int kv0 = t * 64;
        __syncthreads();
        // ---- stage K,V tile (hi/lo split, fragment order) ----
        #pragma unroll
        for (int u = tid; u < 64 * 16; u += 128) {
            int row = u >> 4;          // key index in tile
            int d4  = (u & 15) << 2;
            const size_t src = (size_t)(kv0 + row) * (NKV * HD) + kvh * HD + d4;
            float4 kv = *(const float4*)(K + src);
            float4 vv = *(const float4*)(V + src);
            const float* kp = (const float*)&kv;
            const float* vp = (const float*)&vv;
            #pragma unroll
            for (int f = 0; f < 4; f++) {
                int d = d4 + f;
                // K: n = key, k = d
                int ki = (((d >> 3) * 8 + (row >> 3)) * 32
                          + ((row & 7) * 4 + (d & 3))) * 2 + ((d & 7) >> 2);
                float x = kp[f], hx = t13(x);
                Khi[ki] = hx; Klo[ki] = x - hx;
                // V: n = d, k = key
                int vi = (((row >> 3) * 8 + (d >> 3)) * 32
                          + ((d & 7) * 4 + (row & 3))) * 2 + ((row & 7) >> 2);
                x = vp[f]; hx = t13(x);
                Vhi[vi] = hx; Vlo[vi] = x - hx;
            }
        }
        __syncthreads();

        // ---- S = Q K^T (3-pass tf32) ----
        float s[8][4];
        #pragma unroll
        for (int nt = 0; nt < 8; nt++)
            #pragma unroll
            for (int v = 0; v < 4; v++) s[nt][v] = 0.f;
        #pragma unroll
        for (int k8 = 0; k8 < 8; k8++) {
            #pragma unroll
            for (int nt = 0; nt < 8; nt++) {
                int fb = ((k8 * 8 + nt) * 32 + lane) * 2;
                float2 khv = *(const float2*)&Khi[fb];
                float2 klv = *(const float2*)&Klo[fb];
                uint32_t kh[2] = {__float_as_uint(khv.x), __float_as_uint(khv.y)};
                uint32_t kl[2] = {__float_as_uint(klv.x), __float_as_uint(klv.y)};
                mma8(s[nt], qh[k8], kh);
                mma8(s[nt], qh[k8], kl);
                mma8(s[nt], ql[k8], kh);
            }
        }

        // ---- causal mask (diagonal tile only) ----
        if (t == qt) {
            #pragma unroll
            for (int nt = 0; nt < 8; nt++) {
                int cb = kv0 + nt * 8 + (lane & 3) * 2;
                if (cb > r0)     s[nt][0] = -1e30f;
                if (cb + 1 > r0) s[nt][1] = -1e30f;
                if (cb > r1)     s[nt][2] = -1e30f;
                if (cb + 1 > r1) s[nt][3] = -1e30f;
            }
        }

        // ---- online softmax ----
        float tm0 = -1e30f, tm1 = -1e30f;
        #pragma unroll
        for (int nt = 0; nt < 8; nt++) {
            tm0 = fmaxf(tm0, fmaxf(s[nt][0], s[nt][1]));
            tm1 = fmaxf(tm1, fmaxf(s[nt][2], s[nt][3]));
        }
        tm0 = fmaxf(tm0, __shfl_xor_sync(0xffffffffu, tm0, 1));
        tm0 = fmaxf(tm0, __shfl_xor_sync(0xffffffffu, tm0, 2));
        tm1 = fmaxf(tm1, __shfl_xor_sync(0xffffffffu, tm1, 1));
        tm1 = fmaxf(tm1, __shfl_xor_sync(0xffffffffu, tm1, 2));
        float mn0 = fmaxf(m0, tm0), mn1 = fmaxf(m1, tm1);
        float f0 = __expf(m0 - mn0), f1 = __expf(m1 - mn1);
        m0 = mn0; m1 = mn1;
        float rs0 = 0.f, rs1 = 0.f;
        #pragma unroll
        for (int nt = 0; nt < 8; nt++) {
            s[nt][0] = __expf(s[nt][0] - mn0); rs0 += s[nt][0];
            s[nt][1] = __expf(s[nt][1] - mn0); rs0 += s[nt][1];
            s[nt][2] = __expf(s[nt][2] - mn1); rs1 += s[nt][2];
            s[nt][3] = __expf(s[nt][3] - mn1); rs1 += s[nt][3];
        }
        rs0 += __shfl_xor_sync(0xffffffffu, rs0, 1);
        rs0 += __shfl_xor_sync(0xffffffffu, rs0, 2);
        rs1 += __shfl_xor_sync(0xffffffffu, rs1, 1);
        rs1 += __shfl_xor_sync(0xffffffffu, rs1, 2);
        l0 = l0 * f0 + rs0;
        l1 = l1 * f1 + rs1;
        #pragma unroll
        for (int nt = 0; nt < 8; nt++) {
            o[nt][0] *= f0; o[nt][1] *= f0;
            o[nt][2] *= f1; o[nt][3] *= f1;
        }

        // ---- P: D-layout -> A-layout via padded smem round-trip ----
        #pragma unroll
        for (int nt = 0; nt < 8; nt++) {
            int base = (lane >> 2) * 68 + nt * 8 + (lane & 3) * 2;
            *(float2*)&Ps[base]          = make_float2(s[nt][0], s[nt][1]);
            *(float2*)&Ps[base + 8 * 68] = make_float2(s[nt][2], s[nt][3]);
        }
        __syncwarp();

        // ---- O += P V (V hi/lo 2-pass) ----
        #pragma unroll
        for (int k8 = 0; k8 < 8; k8++) {
            int pc = k8 * 8 + (lane & 3);
            uint32_t pa[4];
            pa[0] = t13u(Ps[(lane >> 2) * 68 + pc]);
            pa[1] = t13u(Ps[((lane >> 2) + 8) * 68 + pc]);
            pa[2] = t13u(Ps[(lane >> 2) * 68 + pc + 4]);
            pa[3] = t13u(Ps[((lane >> 2) + 8) * 68 + pc + 4]);
            #pragma unroll
            for (int nt = 0; nt < 8; nt++) {
                int fb = ((k8 * 8 + nt) * 32 + lane) * 2;
                float2 vhv = *(const float2*)&Vhi[fb];
                float2 vlv = *(const float2*)&Vlo[fb];
                uint32_t vh[2] = {__float_as_uint(vhv.x), __float_as_uint(vhv.y)};
                uint32_t vl[2] = {__float_as_uint(vlv.x), __float_as_uint(vlv.y)};
                mma8(o[nt], pa, vh);
                mma8(o[nt], pa, vl);
            }
        }
        __syncwarp();
    }

    // ---- epilogue ----
    float il0 = 1.0f / l0, il1 = 1.0f / l1;
    float* Ob = O + (size_t)h * HD;
    #pragma unroll
    for (int nt = 0; nt < 8; nt++) {
        int c = nt * 8 + (lane & 3) * 2;
        *(float2*)(Ob + (size_t)r0 * (NH * HD) + c) =
            make_float2(o[nt][0] * il0, o[nt][1] * il0);
        *(float2*)(Ob + (size_t)r1 * (NH * HD) + c) =
            make_float2(o[nt][2] * il1, o[nt][3] * il1);
    }
}

// ---------------- launch ----------------------------------------------------
extern "C" void kernel_launch(void* const* d_in, const int* in_sizes, int n_in,
                              void* d_out, int out_size)
{
    const float* X  = (const float*)d_in[0];
    const float* Wq = (const float*)d_in[1];
    const float* Wk = (const float*)d_in[2];
    const float* Wv = (const float*)d_in[3];
    const float* Wo = (const float*)d_in[4];
    float* out = (float*)d_out;

    float *pQ, *pK, *pV, *pA;
    cudaGetSymbolAddress((void**)&pQ, g_Q);
    cudaGetSymbolAddress((void**)&pK, g_K);
    cudaGetSymbolAddress((void**)&pV, g_V);
    cudaGetSymbolAddress((void**)&pA, g_attn);

    cudaFuncSetAttribute(gemm_mma_kernel,
                         cudaFuncAttributeMaxDynamicSharedMemorySize, GEMM_SMEM);
    cudaFuncSetAttribute(attn_mma_kernel,
                         cudaFuncAttributeMaxDynamicSharedMemorySize, ATT_SMEM);

    // Merged QKV projections (RoPE fused into Q and K epilogues)
    gemm_mma_kernel<<<dim3(12, 16), 256, GEMM_SMEM>>>(
        X,
        Wq, pQ, NH * HD, 1, 8,
        Wk, pK, NKV * HD, 1, 2,
        Wv, pV, NKV * HD, 0);

    // MMA flash attention
    attn_mma_kernel<<<dim3(32, NH), 128, ATT_SMEM>>>(pQ, pK, pV, pA);

    // Output projection
    gemm_mma_kernel<<<dim3(8, 16), 256, GEMM_SMEM>>>(
        pA,
        Wo, out, HID, 0, 8,
        Wo, out, HID, 0, 0,
        Wo, out, HID, 0);
}

// round 7
// speedup vs baseline: 1.9467x; 1.2954x over previous
#include <cuda_runtime.h>
#include <cuda_bf16.h>
#include <math.h>
#include <stdint.h>

// Problem constants
#define S    2048
#define HID  1024
#define NH   16
#define NKV  4
#define HD   64

// ---------------- scratch (device globals; no allocations allowed) ----------
__device__ float g_Q[S * NH * HD];
__device__ float g_K[S * NKV * HD];
__device__ float g_V[S * NKV * HD];
__device__ float g_attn[S * NH * HD];

// ---------------- helpers ----------------------------------------------------
// Split (x,y) into packed bf16x2 hi and bf16x2 lo (residual).
__device__ __forceinline__ void bsplit(float x, float y, uint32_t& hi, uint32_t& lo) {
    __nv_bfloat162 h = __floats2bfloat162_rn(x, y);
    float hx = __bfloat162float(h.x);
    float hy = __bfloat162float(h.y);
    __nv_bfloat162 l = __floats2bfloat162_rn(x - hx, y - hy);
    hi = *(uint32_t*)&h;
    lo = *(uint32_t*)&l;
}

// m16n8k16 bf16 mma, D += A*B
__device__ __forceinline__ void mma16(float* d, const uint32_t* a, const uint32_t* b) {
    asm volatile(
        "mma.sync.aligned.m16n8k16.row.col.f32.bf16.bf16.f32 "
        "{%0,%1,%2,%3}, {%4,%5,%6,%7}, {%8,%9}, {%0,%1,%2,%3};"
        : "+f"(d[0]), "+f"(d[1]), "+f"(d[2]), "+f"(d[3])
        : "r"(a[0]), "r"(a[1]), "r"(a[2]), "r"(a[3]), "r"(b[0]), "r"(b[1]));
}

// ================= tensor-core bf16 GEMM (3xBF16, double-buffered) ===========
// C[M,N] = A[M,1024] @ B[1024,N]. Block tile 64 x 128, BK=32, 128 threads
// (4 warps: 2 M x 2 N; warp tile 32 x 64). hi/lo split done at staging.
// SMEM buffer (u32): Ahi[1024] Alo[1024] Bhi[2048] Blo[2048] = 6144 u32 = 24KB.
#define GEMM_SMEM (2 * 6144 * 4)

__global__ __launch_bounds__(128) void gemm_bf16_kernel(
    const float* __restrict__ A,
    const float* __restrict__ B0, float* __restrict__ C0, int ld0, int rope0, int nx0,
    const float* __restrict__ B1, float* __restrict__ C1, int ld1, int rope1, int nx1,
    const float* __restrict__ B2, float* __restrict__ C2, int ld2, int rope2)
{
    extern __shared__ uint32_t sm[];
    const int tid  = threadIdx.x;
    const int wid  = tid >> 5;
    const int lane = tid & 31;
    const int wm   = wid & 1;      // M warp (2 x 32 rows)
    const int wn   = wid >> 1;     // N warp (2 x 64 cols)
    const int m0   = blockIdx.y * 64;

    const float* B; float* C; int ld, rope, n0;
    {
        int bx = blockIdx.x;
        if (bx < nx0)            { B = B0; C = C0; ld = ld0; rope = rope0; n0 = bx * 128; }
        else if (bx < nx0 + nx1) { B = B1; C = C1; ld = ld1; rope = rope1; n0 = (bx - nx0) * 128; }
        else                     { B = B2; C = C2; ld = ld2; rope = rope2; n0 = (bx - nx0 - nx1) * 128; }
    }

    float acc[2][8][4];
    #pragma unroll
    for (int i = 0; i < 2; i++)
        #pragma unroll
        for (int j = 0; j < 8; j++)
            #pragma unroll
            for (int v = 0; v < 4; v++) acc[i][j][v] = 0.f;

    float4 ar[4];        // A prefetch: 64 rows x 8 q-groups / 128 thr = 4
    float4 br[4][2];     // B prefetch: 16 kpairs x 32 n4 / 128 thr = 4 x 2 rows

    auto load_regs = [&](int ch) {
        const int kc0 = ch * 32;
        #pragma unroll
        for (int i = 0; i < 4; i++) {
            int u = tid + i * 128;
            int row = u >> 3, q = u & 7;
            ar[i] = *(const float4*)(A + (size_t)(m0 + row) * HID + kc0 + q * 4);
        }
        #pragma unroll
        for (int i = 0; i < 4; i++) {
            int u = tid + i * 128;
            int kp = u >> 5, n4 = (u & 31) << 2;
            br[i][0] = *(const float4*)(B + (size_t)(kc0 + 2 * kp)     * ld + n0 + n4);
            br[i][1] = *(const float4*)(B + (size_t)(kc0 + 2 * kp + 1) * ld + n0 + n4);
        }
    };
    auto scatter = [&](int buf) {
        uint32_t* Ah = sm + buf * 6144;
        uint32_t* Al = Ah + 1024;
        uint32_t* Bh = Ah + 2048;
        uint32_t* Bl = Ah + 4096;
        #pragma unroll
        for (int i = 0; i < 4; i++) {
            int u = tid + i * 128;
            int row = u >> 3, q = u & 7;
            int mt = row >> 4, r16 = row & 15;
            const float* v = (const float*)&ar[i];
            #pragma unroll
            for (int f2 = 0; f2 < 2; f2++) {
                int ke = q * 4 + f2 * 2;
                int s  = ke >> 4, kk = ke & 15;
                int c  = (kk >> 1) & 3;
                int rg = (r16 >> 3) | ((kk >= 8) ? 2 : 0);
                int idx = ((s * 4 + mt) * 32 + (((r16 & 7) << 2) | c)) * 4 + rg;
                bsplit(v[f2 * 2], v[f2 * 2 + 1], Ah[idx], Al[idx]);
            }
        }
        #pragma unroll
        for (int i = 0; i < 4; i++) {
            int u = tid + i * 128;
            int kp = u >> 5, n4 = (u & 31) << 2;
            int s  = kp >> 3, c = kp & 3, rg = (kp >> 2) & 1;
            const float* x0 = (const float*)&br[i][0];
            const float* x1 = (const float*)&br[i][1];
            #pragma unroll
            for (int f = 0; f < 4; f++) {
                int n = n4 + f;
                int idx = ((s * 16 + (n >> 3)) * 32 + (((n & 7) << 2) | c)) * 2 + rg;
                bsplit(x0[f], x1[f], Bh[idx], Bl[idx]);
            }
        }
    };
    auto compute = [&](int buf) {
        const uint32_t* Ah = sm + buf * 6144;
        const uint32_t* Al = Ah + 1024;
        const uint32_t* Bh = Ah + 2048;
        const uint32_t* Bl = Ah + 4096;
        #pragma unroll
        for (int s = 0; s < 2; s++) {
            uint32_t a_h[2][4], a_l[2][4];
            #pragma unroll
            for (int mt = 0; mt < 2; mt++) {
                *(uint4*)a_h[mt] = *(const uint4*)&Ah[((s * 4 + wm * 2 + mt) * 32 + lane) * 4];
                *(uint4*)a_l[mt] = *(const uint4*)&Al[((s * 4 + wm * 2 + mt) * 32 + lane) * 4];
            }
            #pragma unroll
            for (int nt = 0; nt < 8; nt++) {
                uint32_t b_h[2], b_l[2];
                *(uint2*)b_h = *(const uint2*)&Bh[((s * 16 + wn * 8 + nt) * 32 + lane) * 2];
                *(uint2*)b_l = *(const uint2*)&Bl[((s * 16 + wn * 8 + nt) * 32 + lane) * 2];
                #pragma unroll
                for (int mt = 0; mt < 2; mt++) {
                    mma16(acc[mt][nt], a_h[mt], b_h);
                    mma16(acc[mt][nt], a_h[mt], b_l);
                    mma16(acc[mt][nt], a_l[mt], b_h);
                }
            }
        }
    };

    load_regs(0);
    scatter(0);
    __syncthreads();
    for (int ch = 0; ch < 32; ch++) {
        if (ch < 31) load_regs(ch + 1);
        compute(ch & 1);
        if (ch < 31) scatter((ch + 1) & 1);
        __syncthreads();
    }

    // ---- epilogue: optional fused RoPE, then store ----
    const float L2T_16 = 13.287712379549449f / 16.0f;  // log2(10000)/16
    #pragma unroll
    for (int mt = 0; mt < 2; mt++) {
        int rbase = m0 + wm * 32 + mt * 16 + (lane >> 2);
        #pragma unroll
        for (int nt = 0; nt < 8; nt++) {
            int c = n0 + (wn * 8 + nt) * 8 + (lane & 3) * 2;
            float inv = 0.f;
            if (rope) {
                int fidx = (c >> 1) & 15;
                inv = exp2f(-(float)fidx * L2T_16);
            }
            #pragma unroll
            for (int half = 0; half < 2; half++) {
                int row = rbase + half * 8;
                float e = acc[mt][nt][half * 2];
                float o = acc[mt][nt][half * 2 + 1];
                if (rope) {
                    float sn, cs;
                    sincosf((float)row * inv, &sn, &cs);
                    float re = e * cs - o * sn;
                    float ro = e * sn + o * cs;
                    e = re; o = ro;
                }
                *(float2*)(C + (size_t)row * ld + c) = make_float2(e, o);
            }
        }
    }
}

// ================= MMA flash attention (bf16 3x, causal, GQA 4:1) ============
// Block = 128 threads (4 warps) = 64 q rows of one head. KV tiles of 64.
// P A-fragments are packed directly from S D-fragments (no smem round-trip).
// SMEM (u32): Kh[2048] Kl[2048] Vh[2048] Vl[2048] = 8192 u32 = 32KB.
#define ATT_SMEM (8192 * 4)

__global__ __launch_bounds__(128) void attn_mma_kernel(
    const float* __restrict__ Q, const float* __restrict__ K,
    const float* __restrict__ V, float* __restrict__ O)
{
    extern __shared__ uint32_t sm[];
    uint32_t* Kh = sm;
    uint32_t* Kl = sm + 2048;
    uint32_t* Vh = sm + 4096;
    uint32_t* Vl = sm + 6144;

    const int tid  = threadIdx.x;
    const int wid  = tid >> 5;
    const int lane = tid & 31;

    const int h   = blockIdx.y;
    const int qt  = gridDim.x - 1 - blockIdx.x;  // heavy tiles first
    const int q0  = qt * 64;
    const int kvh = h >> 2;

    // ---- Q fragments (hi/lo bf16), scaled by 1/8 ----
    const int r0 = q0 + wid * 16 + (lane >> 2);
    const int r1 = r0 + 8;
    const int c2 = (lane & 3) * 2;
    uint32_t qh[4][4], ql[4][4];
    {
        const float* Qb = Q + (size_t)h * HD;
        #pragma unroll
        for (int s = 0; s < 4; s++) {
            float2 v0 = *(const float2*)(Qb + (size_t)r0 * (NH * HD) + s * 16 + c2);
            float2 v1 = *(const float2*)(Qb + (size_t)r1 * (NH * HD) + s * 16 + c2);
            float2 v2 = *(const float2*)(Qb + (size_t)r0 * (NH * HD) + s * 16 + 8 + c2);
            float2 v3 = *(const float2*)(Qb + (size_t)r1 * (NH * HD) + s * 16 + 8 + c2);
            bsplit(v0.x * 0.125f, v0.y * 0.125f, qh[s][0], ql[s][0]);
            bsplit(v1.x * 0.125f, v1.y * 0.125f, qh[s][1], ql[s][1]);
            bsplit(v2.x * 0.125f, v2.y * 0.125f, qh[s][2], ql[s][2]);
            bsplit(v3.x * 0.125f, v3.y * 0.125f, qh[s][3], ql[s][3]);
        }
    }

    float m0 = -1e30f, m1 = -1e30f, l0 = 0.f, l1 = 0.f;
    float o[8][4];
    #pragma unroll
    for (int nt = 0; nt < 8; nt++)
        #pragma unroll
        for (int v = 0; v < 4; v++) o[nt][v] = 0.f;

    for (int t = 0; t <= qt; t++) {
        const int kv0 = t * 64;
        __syncthreads();
        // ---- stage K (B-frag: n=key, k=d) ----
        #pragma unroll
        for (int u = tid; u < 1024; u += 128) {
            int key = u >> 4;
            int d4  = (u & 15) << 2;
            float4 kv = *(const float4*)(K + (size_t)(kv0 + key) * (NKV * HD) + kvh * HD + d4);
            const float* v = (const float*)&kv;
            #pragma unroll
            for (int f2 = 0; f2 < 2; f2++) {
                int de = d4 + f2 * 2;
                int s = de >> 4, kk = de & 15;
                int c = (kk >> 1) & 3, rg = (kk >= 8);
                int idx = ((s * 8 + (key >> 3)) * 32 + (((key & 7) << 2) | c)) * 2 + rg;
                bsplit(v[f2 * 2], v[f2 * 2 + 1], Kh[idx], Kl[idx]);
            }
        }
        // ---- stage V (B-frag: n=d, k=key; pairs along key) ----
        #pragma unroll
        for (int u = tid; u < 512; u += 128) {
            int kp = u >> 4;
            int d4 = (u & 15) << 2;
            const size_t base = (size_t)(kv0 + 2 * kp) * (NKV * HD) + kvh * HD + d4;
            float4 a = *(const float4*)(V + base);
            float4 b = *(const float4*)(V + base + NKV * HD);
            const float* x0 = (const float*)&a;
            const float* x1 = (const float*)&b;
            int s = kp >> 3, c = kp & 3, rg = (kp >> 2) & 1;
            #pragma unroll
            for (int f = 0; f < 4; f++) {
                int d = d4 + f;
                int idx = ((s * 8 + (d >> 3)) * 32 + (((d & 7) << 2) | c)) * 2 + rg;
                bsplit(x0[f], x1[f], Vh[idx], Vl[idx]);
            }
        }
        __syncthreads();

        // ---- S = Q K^T (3xBF16) ----
        float s_[8][4];
        #pragma unroll
        for (int nt = 0; nt < 8; nt++)
            #pragma unroll
            for (int v = 0; v < 4; v++) s_[nt][v] = 0.f;
        #pragma unroll
        for (int s = 0; s < 4; s++) {
            #pragma unroll
            for (int nt = 0; nt < 8; nt++) {
                uint32_t b_h[2], b_l[2];
                *(uint2*)b_h = *(const uint2*)&Kh[((s * 8 + nt) * 32 + lane) * 2];
                *(uint2*)b_l = *(const uint2*)&Kl[((s * 8 + nt) * 32 + lane) * 2];
                mma16(s_[nt], qh[s], b_h);
                mma16(s_[nt], qh[s], b_l);
                mma16(s_[nt], ql[s], b_h);
            }
        }

        // ---- causal mask (diagonal tile only) ----
        if (t == qt) {
            #pragma unroll
            for (int nt = 0; nt < 8; nt++) {
                int cb = kv0 + nt * 8 + c2;
                if (cb > r0)     s_[nt][0] = -1e30f;
                if (cb + 1 > r0) s_[nt][1] = -1e30f;
                if (cb > r1)     s_[nt][2] = -1e30f;
                if (cb + 1 > r1) s_[nt][3] = -1e30f;
            }
        }

        // ---- online softmax ----
        float tm0 = -1e30f, tm1 = -1e30f;
        #pragma unroll
        for (int nt = 0; nt < 8; nt++) {
            tm0 = fmaxf(tm0, fmaxf(s_[nt][0], s_[nt][1]));
            tm1 = fmaxf(tm1, fmaxf(s_[nt][2], s_[nt][3]));
        }
        tm0 = fmaxf(tm0, __shfl_xor_sync(0xffffffffu, tm0, 1));
        tm0 = fmaxf(tm0, __shfl_xor_sync(0xffffffffu, tm0, 2));
        tm1 = fmaxf(tm1, __shfl_xor_sync(0xffffffffu, tm1, 1));
        tm1 = fmaxf(tm1, __shfl_xor_sync(0xffffffffu, tm1, 2));
        float mn0 = fmaxf(m0, tm0), mn1 = fmaxf(m1, tm1);
        float f0 = __expf(m0 - mn0), f1 = __expf(m1 - mn1);
        m0 = mn0; m1 = mn1;
        float rs0 = 0.f, rs1 = 0.f;
        #pragma unroll
        for (int nt = 0; nt < 8; nt++) {
            s_[nt][0] = __expf(s_[nt][0] - mn0); rs0 += s_[nt][0];
            s_[nt][1] = __expf(s_[nt][1] - mn0); rs0 += s_[nt][1];
            s_[nt][2] = __expf(s_[nt][2] - mn1); rs1 += s_[nt][2];
            s_[nt][3] = __expf(s_[nt][3] - mn1); rs1 += s_[nt][3];
        }
        rs0 += __shfl_xor_sync(0xffffffffu, rs0, 1);
        rs0 += __shfl_xor_sync(0xffffffffu, rs0, 2);
        rs1 += __shfl_xor_sync(0xffffffffu, rs1, 1);
        rs1 += __shfl_xor_sync(0xffffffffu, rs1, 2);
        l0 = l0 * f0 + rs0;
        l1 = l1 * f1 + rs1;
        #pragma unroll
        for (int nt = 0; nt < 8; nt++) {
            o[nt][0] *= f0; o[nt][1] *= f0;
            o[nt][2] *= f1; o[nt][3] *= f1;
        }

        // ---- O += P V : P A-fragments packed straight from S D-fragments ----
        #pragma unroll
        for (int s = 0; s < 4; s++) {
            uint32_t ph[4], pl[4];
            bsplit(s_[2 * s][0],     s_[2 * s][1],     ph[0], pl[0]);
            bsplit(s_[2 * s][2],     s_[2 * s][3],     ph[1], pl[1]);
            bsplit(s_[2 * s + 1][0], s_[2 * s + 1][1], ph[2], pl[2]);
            bsplit(s_[2 * s + 1][2], s_[2 * s + 1][3], ph[3], pl[3]);
            #pragma unroll
            for (int nt = 0; nt < 8; nt++) {
                uint32_t v_h[2], v_l[2];
                *(uint2*)v_h = *(const uint2*)&Vh[((s * 8 + nt) * 32 + lane) * 2];
                *(uint2*)v_l = *(const uint2*)&Vl[((s * 8 + nt) * 32 + lane) * 2];
                mma16(o[nt], ph, v_h);
                mma16(o[nt], ph, v_l);
                mma16(o[nt], pl, v_h);
            }
        }
    }

    // ---- epilogue ----
    float il0 = 1.0f / l0, il1 = 1.0f / l1;
    float* Ob = O + (size_t)h * HD;
    #pragma unroll
    for (int nt = 0; nt < 8; nt++) {
        int c = nt * 8 + c2;
        *(float2*)(Ob + (size_t)r0 * (NH * HD) + c) =
            make_float2(o[nt][0] * il0, o[nt][1] * il0);
        *(float2*)(Ob + (size_t)r1 * (NH * HD) + c) =
            make_float2(o[nt][2] * il1, o[nt][3] * il1);
    }
}

// ---------------- launch ----------------------------------------------------
extern "C" void kernel_launch(void* const* d_in, const int* in_sizes, int n_in,
                              void* d_out, int out_size)
{
    const float* X  = (const float*)d_in[0];
    const float* Wq = (const float*)d_in[1];
    const float* Wk = (const float*)d_in[2];
    const float* Wv = (const float*)d_in[3];
    const float* Wo = (const float*)d_in[4];
    float* out = (float*)d_out;

    float *pQ, *pK, *pV, *pA;
    cudaGetSymbolAddress((void**)&pQ, g_Q);
    cudaGetSymbolAddress((void**)&pK, g_K);
    cudaGetSymbolAddress((void**)&pV, g_V);
    cudaGetSymbolAddress((void**)&pA, g_attn);

    cudaFuncSetAttribute(gemm_bf16_kernel,
                         cudaFuncAttributeMaxDynamicSharedMemorySize, GEMM_SMEM);
    cudaFuncSetAttribute(attn_mma_kernel,
                         cudaFuncAttributeMaxDynamicSharedMemorySize, ATT_SMEM);

    // Merged QKV projections (RoPE fused into Q and K epilogues)
    gemm_bf16_kernel<<<dim3(12, 32), 128, GEMM_SMEM>>>(
        X,
        Wq, pQ, NH * HD, 1, 8,
        Wk, pK, NKV * HD, 1, 2,
        Wv, pV, NKV * HD, 0);

    // MMA flash attention
    attn_mma_kernel<<<dim3(32, NH), 128, ATT_SMEM>>>(pQ, pK, pV, pA);

    // Output projection
    gemm_bf16_kernel<<<dim3(8, 32), 128, GEMM_SMEM>>>(
        pA,
        Wo, out, HID, 0, 8,
        Wo, out, HID, 0, 0,
        Wo, out, HID, 0);
}

// round 8
// speedup vs baseline: 1.9836x; 1.0190x over previous
#include <cuda_runtime.h>
#include <cuda_bf16.h>
#include <math.h>
#include <stdint.h>

// Problem constants
#define S    2048
#define HID  1024
#define NH   16
#define NKV  4
#define HD   64

// ---------------- scratch (device globals; no allocations allowed) ----------
__device__ float g_Q[S * NH * HD];
__device__ float g_K[S * NKV * HD];
__device__ float g_V[S * NKV * HD];
__device__ float g_attn[S * NH * HD];

// ---------------- helpers ----------------------------------------------------
// Split (x,y) into packed bf16x2 hi and bf16x2 lo (residual).
__device__ __forceinline__ void bsplit(float x, float y, uint32_t& hi, uint32_t& lo) {
    __nv_bfloat162 h = __floats2bfloat162_rn(x, y);
    float hx = __bfloat162float(h.x);
    float hy = __bfloat162float(h.y);
    __nv_bfloat162 l = __floats2bfloat162_rn(x - hx, y - hy);
    hi = *(uint32_t*)&h;
    lo = *(uint32_t*)&l;
}

// m16n8k16 bf16 mma, D += A*B
__device__ __forceinline__ void mma16(float* d, const uint32_t* a, const uint32_t* b) {
    asm volatile(
        "mma.sync.aligned.m16n8k16.row.col.f32.bf16.bf16.f32 "
        "{%0,%1,%2,%3}, {%4,%5,%6,%7}, {%8,%9}, {%0,%1,%2,%3};"
        : "+f"(d[0]), "+f"(d[1]), "+f"(d[2]), "+f"(d[3])
        : "r"(a[0]), "r"(a[1]), "r"(a[2]), "r"(a[3]), "r"(b[0]), "r"(b[1]));
}

// ================= tensor-core bf16 GEMM (3xBF16, double-buffered) ===========
// C[M,N] = A[M,1024] @ B[1024,N]. Block tile 64 x 128, BK=32, 128 threads
// (4 warps: 2 M x 2 N; warp tile 32 x 64). hi/lo split done at staging.
// Compute is pass-major: same-acc MMA reuse distance = 8 (no RAW stalls).
// SMEM buffer (u32): Ahi[1024] Alo[1024] Bhi[2048] Blo[2048] = 6144 u32 = 24KB.
#define GEMM_SMEM (2 * 6144 * 4)

__global__ __launch_bounds__(128) void gemm_bf16_kernel(
    const float* __restrict__ A,
    const float* __restrict__ B0, float* __restrict__ C0, int ld0, int rope0, int nx0,
    const float* __restrict__ B1, float* __restrict__ C1, int ld1, int rope1, int nx1,
    const float* __restrict__ B2, float* __restrict__ C2, int ld2, int rope2)
{
    extern __shared__ uint32_t sm[];
    const int tid  = threadIdx.x;
    const int wid  = tid >> 5;
    const int lane = tid & 31;
    const int wm   = wid & 1;      // M warp (2 x 32 rows)
    const int wn   = wid >> 1;     // N warp (2 x 64 cols)
    const int m0   = blockIdx.y * 64;

    const float* B; float* C; int ld, rope, n0;
    {
        int bx = blockIdx.x;
        if (bx < nx0)            { B = B0; C = C0; ld = ld0; rope = rope0; n0 = bx * 128; }
        else if (bx < nx0 + nx1) { B = B1; C = C1; ld = ld1; rope = rope1; n0 = (bx - nx0) * 128; }
        else                     { B = B2; C = C2; ld = ld2; rope = rope2; n0 = (bx - nx0 - nx1) * 128; }
    }

    float acc[2][8][4];
    #pragma unroll
    for (int i = 0; i < 2; i++)
        #pragma unroll
        for (int j = 0; j < 8; j++)
            #pragma unroll
            for (int v = 0; v < 4; v++) acc[i][j][v] = 0.f;

    float4 ar[4];        // A prefetch
    float4 br[4][2];     // B prefetch

    auto load_regs = [&](int ch) {
        const int kc0 = ch * 32;
        #pragma unroll
        for (int i = 0; i < 4; i++) {
            int u = tid + i * 128;
            int row = u >> 3, q = u & 7;
            ar[i] = *(const float4*)(A + (size_t)(m0 + row) * HID + kc0 + q * 4);
        }
        #pragma unroll
        for (int i = 0; i < 4; i++) {
            int u = tid + i * 128;
            int kp = u >> 5, n4 = (u & 31) << 2;
            br[i][0] = *(const float4*)(B + (size_t)(kc0 + 2 * kp)     * ld + n0 + n4);
            br[i][1] = *(const float4*)(B + (size_t)(kc0 + 2 * kp + 1) * ld + n0 + n4);
        }
    };
    auto scatter = [&](int buf) {
        uint32_t* Ah = sm + buf * 6144;
        uint32_t* Al = Ah + 1024;
        uint32_t* Bh = Ah + 2048;
        uint32_t* Bl = Ah + 4096;
        #pragma unroll
        for (int i = 0; i < 4; i++) {
            int u = tid + i * 128;
            int row = u >> 3, q = u & 7;
            int mt = row >> 4, r16 = row & 15;
            const float* v = (const float*)&ar[i];
            #pragma unroll
            for (int f2 = 0; f2 < 2; f2++) {
                int ke = q * 4 + f2 * 2;
                int s  = ke >> 4, kk = ke & 15;
                int c  = (kk >> 1) & 3;
                int rg = (r16 >> 3) | ((kk >= 8) ? 2 : 0);
                int idx = ((s * 4 + mt) * 32 + (((r16 & 7) << 2) | c)) * 4 + rg;
                bsplit(v[f2 * 2], v[f2 * 2 + 1], Ah[idx], Al[idx]);
            }
        }
        #pragma unroll
        for (int i = 0; i < 4; i++) {
            int u = tid + i * 128;
            int kp = u >> 5, n4 = (u & 31) << 2;
            int s  = kp >> 3, c = kp & 3, rg = (kp >> 2) & 1;
            const float* x0 = (const float*)&br[i][0];
            const float* x1 = (const float*)&br[i][1];
            #pragma unroll
            for (int f = 0; f < 4; f++) {
                int n = n4 + f;
                int idx = ((s * 16 + (n >> 3)) * 32 + (((n & 7) << 2) | c)) * 2 + rg;
                bsplit(x0[f], x1[f], Bh[idx], Bl[idx]);
            }
        }
    };
    auto compute = [&](int buf) {
        const uint32_t* Ah = sm + buf * 6144;
        const uint32_t* Al = Ah + 1024;
        const uint32_t* Bh = Ah + 2048;
        const uint32_t* Bl = Ah + 4096;
        #pragma unroll
        for (int s = 0; s < 2; s++) {
            uint32_t a_h[2][4], a_l[2][4];
            #pragma unroll
            for (int mt = 0; mt < 2; mt++) {
                *(uint4*)a_h[mt] = *(const uint4*)&Ah[((s * 4 + wm * 2 + mt) * 32 + lane) * 4];
                *(uint4*)a_l[mt] = *(const uint4*)&Al[((s * 4 + wm * 2 + mt) * 32 + lane) * 4];
            }
            #pragma unroll
            for (int ntb = 0; ntb < 2; ntb++) {
                uint32_t b_h[4][2], b_l[4][2];
                #pragma unroll
                for (int j = 0; j < 4; j++) {
                    int nt = wn * 8 + ntb * 4 + j;
                    *(uint2*)b_h[j] = *(const uint2*)&Bh[((s * 16 + nt) * 32 + lane) * 2];
                    *(uint2*)b_l[j] = *(const uint2*)&Bl[((s * 16 + nt) * 32 + lane) * 2];
                }
                // pass-major: same-acc reuse distance = 8 MMAs
                #pragma unroll
                for (int j = 0; j < 4; j++)
                    #pragma unroll
                    for (int mt = 0; mt < 2; mt++)
                        mma16(acc[mt][ntb * 4 + j], a_h[mt], b_h[j]);
                #pragma unroll
                for (int j = 0; j < 4; j++)
                    #pragma unroll
                    for (int mt = 0; mt < 2; mt++)
                        mma16(acc[mt][ntb * 4 + j], a_h[mt], b_l[j]);
                #pragma unroll
                for (int j = 0; j < 4; j++)
                    #pragma unroll
                    for (int mt = 0; mt < 2; mt++)
                        mma16(acc[mt][ntb * 4 + j], a_l[mt], b_h[j]);
            }
        }
    };

    load_regs(0);
    scatter(0);
    __syncthreads();
    for (int ch = 0; ch < 32; ch++) {
        if (ch < 31) load_regs(ch + 1);
        compute(ch & 1);
        if (ch < 31) scatter((ch + 1) & 1);
        __syncthreads();
    }

    // ---- epilogue: optional fused RoPE, then store ----
    const float L2T_16 = 13.287712379549449f / 16.0f;  // log2(10000)/16
    #pragma unroll
    for (int mt = 0; mt < 2; mt++) {
        int rbase = m0 + wm * 32 + mt * 16 + (lane >> 2);
        #pragma unroll
        for (int nt = 0; nt < 8; nt++) {
            int c = n0 + (wn * 8 + nt) * 8 + (lane & 3) * 2;
            float inv = 0.f;
            if (rope) {
                int fidx = (c >> 1) & 15;
                inv = exp2f(-(float)fidx * L2T_16);
            }
            #pragma unroll
            for (int half = 0; half < 2; half++) {
                int row = rbase + half * 8;
                float e = acc[mt][nt][half * 2];
                float o = acc[mt][nt][half * 2 + 1];
                if (rope) {
                    float sn, cs;
                    sincosf((float)row * inv, &sn, &cs);
                    float re = e * cs - o * sn;
                    float ro = e * sn + o * cs;
                    e = re; o = ro;
                }
                *(float2*)(C + (size_t)row * ld + c) = make_float2(e, o);
            }
        }
    }
}

// ================= MMA flash attention (bf16 3x, causal, GQA 4:1) ============
// Block = 128 threads (4 warps) = 64 q rows of one head. KV tiles of 64.
// Pass-major MMA ordering throughout. SMEM 32KB.
#define ATT_SMEM (8192 * 4)

__global__ __launch_bounds__(128) void attn_mma_kernel(
    const float* __restrict__ Q, const float* __restrict__ K,
    const float* __restrict__ V, float* __restrict__ O)
{
    extern __shared__ uint32_t sm[];
    uint32_t* Kh = sm;
    uint32_t* Kl = sm + 2048;
    uint32_t* Vh = sm + 4096;
    uint32_t* Vl = sm + 6144;

    const int tid  = threadIdx.x;
    const int wid  = tid >> 5;
    const int lane = tid & 31;

    const int h   = blockIdx.y;
    const int qt  = gridDim.x - 1 - blockIdx.x;  // heavy tiles first
    const int q0  = qt * 64;
    const int kvh = h >> 2;

    // ---- Q fragments (hi/lo bf16), scaled by 1/8 ----
    const int r0 = q0 + wid * 16 + (lane >> 2);
    const int r1 = r0 + 8;
    const int c2 = (lane & 3) * 2;
    uint32_t qh[4][4], ql[4][4];
    {
        const float* Qb = Q + (size_t)h * HD;
        #pragma unroll
        for (int s = 0; s < 4; s++) {
            float2 v0 = *(const float2*)(Qb + (size_t)r0 * (NH * HD) + s * 16 + c2);
            float2 v1 = *(const float2*)(Qb + (size_t)r1 * (NH * HD) + s * 16 + c2);
            float2 v2 = *(const float2*)(Qb + (size_t)r0 * (NH * HD) + s * 16 + 8 + c2);
            float2 v3 = *(const float2*)(Qb + (size_t)r1 * (NH * HD) + s * 16 + 8 + c2);
            bsplit(v0.x * 0.125f, v0.y * 0.125f, qh[s][0], ql[s][0]);
            bsplit(v1.x * 0.125f, v1.y * 0.125f, qh[s][1], ql[s][1]);
            bsplit(v2.x * 0.125f, v2.y * 0.125f, qh[s][2], ql[s][2]);
            bsplit(v3.x * 0.125f, v3.y * 0.125f, qh[s][3], ql[s][3]);
        }
    }

    float m0 = -1e30f, m1 = -1e30f, l0 = 0.f, l1 = 0.f;
    float o[8][4];
    #pragma unroll
    for (int nt = 0; nt < 8; nt++)
        #pragma unroll
        for (int v = 0; v < 4; v++) o[nt][v] = 0.f;

    for (int t = 0; t <= qt; t++) {
        const int kv0 = t * 64;
        __syncthreads();
        // ---- stage K (B-frag: n=key, k=d) ----
        #pragma unroll
        for (int u = tid; u < 1024; u += 128) {
            int key = u >> 4;
            int d4  = (u & 15) << 2;
            float4 kv = *(const float4*)(K + (size_t)(kv0 + key) * (NKV * HD) + kvh * HD + d4);
            const float* v = (const float*)&kv;
            #pragma unroll
            for (int f2 = 0; f2 < 2; f2++) {
                int de = d4 + f2 * 2;
                int s = de >> 4, kk = de & 15;
                int c = (kk >> 1) & 3, rg = (kk >= 8);
                int idx = ((s * 8 + (key >> 3)) * 32 + (((key & 7) << 2) | c)) * 2 + rg;
                bsplit(v[f2 * 2], v[f2 * 2 + 1], Kh[idx], Kl[idx]);
            }
        }
        // ---- stage V (B-frag: n=d, k=key; pairs along key) ----
        #pragma unroll
        for (int u = tid; u < 512; u += 128) {
            int kp = u >> 4;
            int d4 = (u & 15) << 2;
            const size_t base = (size_t)(kv0 + 2 * kp) * (NKV * HD) + kvh * HD + d4;
            float4 a = *(const float4*)(V + base);
            float4 b = *(const float4*)(V + base + NKV * HD);
            const float* x0 = (const float*)&a;
            const float* x1 = (const float*)&b;
            int s = kp >> 3, c = kp & 3, rg = (kp >> 2) & 1;
            #pragma unroll
            for (int f = 0; f < 4; f++) {
                int d = d4 + f;
                int idx = ((s * 8 + (d >> 3)) * 32 + (((d & 7) << 2) | c)) * 2 + rg;
                bsplit(x0[f], x1[f], Vh[idx], Vl[idx]);
            }
        }
        __syncthreads();

        // ---- S = Q K^T (3xBF16, pass-major) ----
        float s_[8][4];
        #pragma unroll
        for (int nt = 0; nt < 8; nt++)
            #pragma unroll
            for (int v = 0; v < 4; v++) s_[nt][v] = 0.f;
        #pragma unroll
        for (int s = 0; s < 4; s++) {
            #pragma unroll
            for (int ntb = 0; ntb < 2; ntb++) {
                uint32_t k_h[4][2], k_l[4][2];
                #pragma unroll
                for (int j = 0; j < 4; j++) {
                    int nt = ntb * 4 + j;
                    *(uint2*)k_h[j] = *(const uint2*)&Kh[((s * 8 + nt) * 32 + lane) * 2];
                    *(uint2*)k_l[j] = *(const uint2*)&Kl[((s * 8 + nt) * 32 + lane) * 2];
                }
                #pragma unroll
                for (int j = 0; j < 4; j++) mma16(s_[ntb * 4 + j], qh[s], k_h[j]);
                #pragma unroll
                for (int j = 0; j < 4; j++) mma16(s_[ntb * 4 + j], qh[s], k_l[j]);
                #pragma unroll
                for (int j = 0; j < 4; j++) mma16(s_[ntb * 4 + j], ql[s], k_h[j]);
            }
        }

        // ---- causal mask (diagonal tile only) ----
        if (t == qt) {
            #pragma unroll
            for (int nt = 0; nt < 8; nt++) {
                int cb = kv0 + nt * 8 + c2;
                if (cb > r0)     s_[nt][0] = -1e30f;
                if (cb + 1 > r0) s_[nt][1] = -1e30f;
                if (cb > r1)     s_[nt][2] = -1e30f;
                if (cb + 1 > r1) s_[nt][3] = -1e30f;
            }
        }

        // ---- online softmax ----
        float tm0 = -1e30f, tm1 = -1e30f;
        #pragma unroll
        for (int nt = 0; nt < 8; nt++) {
            tm0 = fmaxf(tm0, fmaxf(s_[nt][0], s_[nt][1]));
            tm1 = fmaxf(tm1, fmaxf(s_[nt][2], s_[nt][3]));
        }
        tm0 = fmaxf(tm0, __shfl_xor_sync(0xffffffffu, tm0, 1));
        tm0 = fmaxf(tm0, __shfl_xor_sync(0xffffffffu, tm0, 2));
        tm1 = fmaxf(tm1, __shfl_xor_sync(0xffffffffu, tm1, 1));
        tm1 = fmaxf(tm1, __shfl_xor_sync(0xffffffffu, tm1, 2));
        float mn0 = fmaxf(m0, tm0), mn1 = fmaxf(m1, tm1);
        float f0 = __expf(m0 - mn0), f1 = __expf(m1 - mn1);
        m0 = mn0; m1 = mn1;
        float rs0 = 0.f, rs1 = 0.f;
        #pragma unroll
        for (int nt = 0; nt < 8; nt++) {
            s_[nt][0] = __expf(s_[nt][0] - mn0); rs0 += s_[nt][0];
            s_[nt][1] = __expf(s_[nt][1] - mn0); rs0 += s_[nt][1];
            s_[nt][2] = __expf(s_[nt][2] - mn1); rs1 += s_[nt][2];
            s_[nt][3] = __expf(s_[nt][3] - mn1); rs1 += s_[nt][3];
        }
        rs0 += __shfl_xor_sync(0xffffffffu, rs0, 1);
        rs0 += __shfl_xor_sync(0xffffffffu, rs0, 2);
        rs1 += __shfl_xor_sync(0xffffffffu, rs1, 1);
        rs1 += __shfl_xor_sync(0xffffffffu, rs1, 2);
        l0 = l0 * f0 + rs0;
        l1 = l1 * f1 + rs1;
        #pragma unroll
        for (int nt = 0; nt < 8; nt++) {
            o[nt][0] *= f0; o[nt][1] *= f0;
            o[nt][2] *= f1; o[nt][3] *= f1;
        }

        // ---- O += P V (pass-major; P A-frags packed from S D-frags) ----
        #pragma unroll
        for (int s = 0; s < 4; s++) {
            uint32_t ph[4], pl[4];
            bsplit(s_[2 * s][0],     s_[2 * s][1],     ph[0], pl[0]);
            bsplit(s_[2 * s][2],     s_[2 * s][3],     ph[1], pl[1]);
            bsplit(s_[2 * s + 1][0], s_[2 * s + 1][1], ph[2], pl[2]);
            bsplit(s_[2 * s + 1][2], s_[2 * s + 1][3], ph[3], pl[3]);
            #pragma unroll
            for (int ntb = 0; ntb < 2; ntb++) {
                uint32_t v_h[4][2], v_l[4][2];
                #pragma unroll
                for (int j = 0; j < 4; j++) {
                    int nt = ntb * 4 + j;
                    *(uint2*)v_h[j] = *(const uint2*)&Vh[((s * 8 + nt) * 32 + lane) * 2];
                    *(uint2*)v_l[j] = *(const uint2*)&Vl[((s * 8 + nt) * 32 + lane) * 2];
                }
                #pragma unroll
                for (int j = 0; j < 4; j++) mma16(o[ntb * 4 + j], ph, v_h[j]);
                #pragma unroll
                for (int j = 0; j < 4; j++) mma16(o[ntb * 4 + j], ph, v_l[j]);
                #pragma unroll
                for (int j = 0; j < 4; j++) mma16(o[ntb * 4 + j], pl, v_h[j]);
            }
        }
    }

    // ---- epilogue ----
    float il0 = 1.0f / l0, il1 = 1.0f / l1;
    float* Ob = O + (size_t)h * HD;
    #pragma unroll
    for (int nt = 0; nt < 8; nt++) {
        int c = nt * 8 + c2;
        *(float2*)(Ob + (size_t)r0 * (NH * HD) + c) =
            make_float2(o[nt][0] * il0, o[nt][1] * il0);
        *(float2*)(Ob + (size_t)r1 * (NH * HD) + c) =
            make_float2(o[nt][2] * il1, o[nt][3] * il1);
    }
}

// ---------------- launch ----------------------------------------------------
extern "C" void kernel_launch(void* const* d_in, const int* in_sizes, int n_in,
                              void* d_out, int out_size)
{
    const float* X  = (const float*)d_in[0];
    const float* Wq = (const float*)d_in[1];
    const float* Wk = (const float*)d_in[2];
    const float* Wv = (const float*)d_in[3];
    const float* Wo = (const float*)d_in[4];
    float* out = (float*)d_out;

    float *pQ, *pK, *pV, *pA;
    cudaGetSymbolAddress((void**)&pQ, g_Q);
    cudaGetSymbolAddress((void**)&pK, g_K);
    cudaGetSymbolAddress((void**)&pV, g_V);
    cudaGetSymbolAddress((void**)&pA, g_attn);

    cudaFuncSetAttribute(gemm_bf16_kernel,
                         cudaFuncAttributeMaxDynamicSharedMemorySize, GEMM_SMEM);
    cudaFuncSetAttribute(attn_mma_kernel,
                         cudaFuncAttributeMaxDynamicSharedMemorySize, ATT_SMEM);

    // Merged QKV projections (RoPE fused into Q and K epilogues)
    gemm_bf16_kernel<<<dim3(12, 32), 128, GEMM_SMEM>>>(
        X,
        Wq, pQ, NH * HD, 1, 8,
        Wk, pK, NKV * HD, 1, 2,
        Wv, pV, NKV * HD, 0);

    // MMA flash attention
    attn_mma_kernel<<<dim3(32, NH), 128, ATT_SMEM>>>(pQ, pK, pV, pA);

    // Output projection
    gemm_bf16_kernel<<<dim3(8, 32), 128, GEMM_SMEM>>>(
        pA,
        Wo, out, HID, 0, 8,
        Wo, out, HID, 0, 0,
        Wo, out, HID, 0);
}

// round 9
// speedup vs baseline: 6.4343x; 3.2438x over previous
#include <cuda_runtime.h>
#include <cuda_bf16.h>
#include <math.h>
#include <stdint.h>

// Problem constants
#define S    2048
#define HID  1024
#define NH   16
#define NKV  4
#define HD   64

// ---------------- fragment-ordered scratch (device globals) -----------------
// A-fragment layout (per 64-row m-block, per k32 chunk, 1024 u32):
//   idx = ((s*4+mt)*32 + lane)*4 + rg   [validated R7/R8 mapping]
// B-fragment layout (per 128-col n-block, per k32 chunk, 2048 u32):
//   idx = ((s*16+nt)*32 + lane)*2 + rg
__device__ uint32_t gXh[32 * 32 * 1024], gXl[32 * 32 * 1024];   // X A-frag
__device__ uint32_t gWh[12 * 32 * 2048], gWl[12 * 32 * 2048];   // Wq|Wk|Wv B-frag
__device__ uint32_t gWoh[8 * 32 * 2048], gWol[8 * 32 * 2048];   // Wo B-frag
__device__ uint32_t gQh[16 * 32 * 2048], gQl[16 * 32 * 2048];   // Q attn A-frag
__device__ uint32_t gKh[4 * 32 * 2048],  gKl[4 * 32 * 2048];    // K attn B-frag
__device__ uint32_t gVh[4 * 32 * 2048],  gVl[4 * 32 * 2048];    // V attn B-frag
__device__ uint32_t gAh[32 * 32 * 1024], gAl[32 * 32 * 1024];   // attn out A-frag

// ---------------- helpers ----------------------------------------------------
__device__ __forceinline__ void bsplit(float x, float y, uint32_t& hi, uint32_t& lo) {
    __nv_bfloat162 h = __floats2bfloat162_rn(x, y);
    float hx = __bfloat162float(h.x);
    float hy = __bfloat162float(h.y);
    __nv_bfloat162 l = __floats2bfloat162_rn(x - hx, y - hy);
    hi = *(uint32_t*)&h;
    lo = *(uint32_t*)&l;
}

__device__ __forceinline__ void mma16(float* d, const uint32_t* a, const uint32_t* b) {
    asm volatile(
        "mma.sync.aligned.m16n8k16.row.col.f32.bf16.bf16.f32 "
        "{%0,%1,%2,%3}, {%4,%5,%6,%7}, {%8,%9}, {%0,%1,%2,%3};"
        : "+f"(d[0]), "+f"(d[1]), "+f"(d[2]), "+f"(d[3])
        : "r"(a[0]), "r"(a[1]), "r"(a[2]), "r"(a[3]), "r"(b[0]), "r"(b[1]));
}

__device__ __forceinline__ void cp16(uint32_t saddr, const void* g) {
    asm volatile("cp.async.cg.shared.global [%0], [%1], 16;" :: "r"(saddr), "l"(g));
}
#define CP_COMMIT asm volatile("cp.async.commit_group;" ::: "memory")
#define CP_WAIT0  asm volatile("cp.async.wait_group 0;" ::: "memory")
#define CP_WAIT1  asm volatile("cp.async.wait_group 1;" ::: "memory")

#define L2T16 (13.287712379549449f / 16.0f)   // log2(10000)/16

// ================= conversion kernels =======================================
// X[row][k] -> A-frag hi/lo
__global__ void convA_kernel(const float* __restrict__ X,
                             uint32_t* __restrict__ Gh, uint32_t* __restrict__ Gl)
{
    int idx = blockIdx.x * blockDim.x + threadIdx.x;   // over S*512 k-pairs
    if (idx >= S * 512) return;
    int row = idx >> 9;
    int k   = (idx & 511) * 2;
    float2 v = *(const float2*)(X + (size_t)row * HID + k);
    uint32_t h, l;
    bsplit(v.x, v.y, h, l);
    int mb = row >> 6, ch = k >> 5;
    int r = row & 63, ke = k & 31;
    int mt = r >> 4, r16 = r & 15;
    int s = ke >> 4, kk = ke & 15;
    int c = (kk >> 1) & 3;
    int rg = (r16 >> 3) | ((kk & 8) ? 2 : 0);
    int ln = ((r16 & 7) << 2) | c;
    int a = ((mb * 32 + ch) << 10) + ((((s * 4 + mt) << 5) + ln) << 2) + rg;
    Gh[a] = h; Gl[a] = l;
}

// W[k][n] (K=1024 x N) -> B-frag hi/lo at block offset nb_base
__global__ void convW_kernel(const float* __restrict__ W, int N,
                             uint32_t* __restrict__ Gh, uint32_t* __restrict__ Gl,
                             int nb_base)
{
    int idx = blockIdx.x * blockDim.x + threadIdx.x;   // over 512*N
    if (idx >= 512 * N) return;
    int kp = idx / N;
    int n  = idx - kp * N;
    int k = kp * 2;
    float x0 = W[(size_t)k * N + n];
    float x1 = W[(size_t)(k + 1) * N + n];
    uint32_t h, l;
    bsplit(x0, x1, h, l);
    int nb = n >> 7, nn = n & 127, nt = nn >> 3;
    int ch = k >> 5, kpc = kp & 15;
    int s = kpc >> 3, c = kpc & 3, rg = (kpc >> 2) & 1;
    int bidx = ((((s * 16 + nt) << 5) + (((nn & 7) << 2) | c)) << 1) + rg;
    int a = (((nb_base + nb) * 32 + ch) << 11) + bidx;
    Gh[a] = h; Gl[a] = l;
}

// ================= fragment GEMM (3xBF16, cp.async double-buffered) ==========
// Block: 64(M) x 128(N), BK=32, 128 threads (wm in M, wn in N).
// Buffer (u32): Ah[1024] Al[1024] Bh[2048] Bl[2048] = 6144; two buffers.
#define GEMM_SMEM (2 * 6144 * 4)

__global__ __launch_bounds__(128, 3) void gemm_frag_kernel(
    const uint32_t* __restrict__ Agh, const uint32_t* __restrict__ Agl,
    const uint32_t* __restrict__ Wgh, const uint32_t* __restrict__ Wgl,
    float* __restrict__ Cout, int qkv)
{
    extern __shared__ uint32_t sm[];
    const uint32_t sb = (uint32_t)__cvta_generic_to_shared(sm);
    const int tid  = threadIdx.x;
    const int wid  = tid >> 5;
    const int lane = tid & 31;
    const int wm   = wid & 1;
    const int wn   = wid >> 1;
    const int mb   = blockIdx.y;
    const int bx   = blockIdx.x;
    const int m0   = mb * 64;

    const uint32_t* Ah_src = Agh + ((size_t)mb << 15);       // mb*32*1024
    const uint32_t* Al_src = Agl + ((size_t)mb << 15);
    const uint32_t* Bh_src = Wgh + ((size_t)bx << 16);       // bx*32*2048
    const uint32_t* Bl_src = Wgl + ((size_t)bx << 16);

    float acc[2][8][4];
    #pragma unroll
    for (int i = 0; i < 2; i++)
        #pragma unroll
        for (int j = 0; j < 8; j++)
            #pragma unroll
            for (int v = 0; v < 4; v++) acc[i][j][v] = 0.f;

    auto issue = [&](int ch, int buf) {
        uint32_t db = sb + buf * 6144 * 4;
        #pragma unroll
        for (int i = 0; i < 2; i++) {
            int j = tid + i * 128;
            cp16(db + j * 16,             Ah_src + (ch << 10) + j * 4);
            cp16(db + 4096 + j * 16,      Al_src + (ch << 10) + j * 4);
        }
        #pragma unroll
        for (int i = 0; i < 4; i++) {
            int j = tid + i * 128;
            cp16(db + 8192 + j * 16,      Bh_src + (ch << 11) + j * 4);
            cp16(db + 16384 + j * 16,     Bl_src + (ch << 11) + j * 4);
        }
    };
    auto compute = [&](int buf) {
        const uint32_t* Ah = sm + buf * 6144;
        const uint32_t* Al = Ah + 1024;
        const uint32_t* Bh = Ah + 2048;
        const uint32_t* Bl = Ah + 4096;
        #pragma unroll
        for (int s = 0; s < 2; s++) {
            uint32_t a_h[2][4], a_l[2][4];
            #pragma unroll
            for (int mt = 0; mt < 2; mt++) {
                *(uint4*)a_h[mt] = *(const uint4*)&Ah[((s * 4 + wm * 2 + mt) * 32 + lane) * 4];
                *(uint4*)a_l[mt] = *(const uint4*)&Al[((s * 4 + wm * 2 + mt) * 32 + lane) * 4];
            }
            #pragma unroll
            for (int ntb = 0; ntb < 2; ntb++) {
                uint32_t b_h[4][2], b_l[4][2];
                #pragma unroll
                for (int j = 0; j < 4; j++) {
                    int nt = wn * 8 + ntb * 4 + j;
                    *(uint2*)b_h[j] = *(const uint2*)&Bh[((s * 16 + nt) * 32 + lane) * 2];
                    *(uint2*)b_l[j] = *(const uint2*)&Bl[((s * 16 + nt) * 32 + lane) * 2];
                }
                #pragma unroll
                for (int j = 0; j < 4; j++)
                    #pragma unroll
                    for (int mt = 0; mt < 2; mt++) {
                        mma16(acc[mt][ntb * 4 + j], a_h[mt], b_h[j]);
                        mma16(acc[mt][ntb * 4 + j], a_h[mt], b_l[j]);
                        mma16(acc[mt][ntb * 4 + j], a_l[mt], b_h[j]);
                    }
            }
        }
    };

    issue(0, 0); CP_COMMIT;
    for (int ch = 0; ch < 32; ch++) {
        if (ch < 31) { issue(ch + 1, (ch + 1) & 1); CP_COMMIT; }
        if (ch < 31) { CP_WAIT1; } else { CP_WAIT0; }
        __syncthreads();
        compute(ch & 1);
        __syncthreads();
    }

    // ---- epilogue ----
    const int mode = qkv ? (bx < 8 ? 1 : (bx < 10 ? 2 : 3)) : 0;

    #pragma unroll
    for (int mt = 0; mt < 2; mt++) {
        #pragma unroll
        for (int nt = 0; nt < 8; nt++) {
            const int nglob = wn * 8 + nt;
            const int nn = nglob & 7;
            float v0 = acc[mt][nt][0], v1 = acc[mt][nt][1];
            float v2 = acc[mt][nt][2], v3 = acc[mt][nt][3];

            if (mode == 0) {
                int row = m0 + wm * 32 + mt * 16 + (lane >> 2);
                int col = bx * 128 + nglob * 8 + (lane & 3) * 2;
                *(float2*)(Cout + (size_t)row * HID + col) = make_float2(v0, v1);
                *(float2*)(Cout + (size_t)(row + 8) * HID + col) = make_float2(v2, v3);
            } else if (mode == 1) {          // Q: RoPE + 1/8 scale -> attn A-frag
                int h2 = bx * 2 + (nglob >> 3);
                int fidx = (nn * 4 + (lane & 3)) & 15;
                float inv = exp2f(-(float)fidx * L2T16);
                uint32_t base = ((uint32_t)(h2 * 32 + mb) << 11)
                              + (((wm * 2 + mt) * 4 + (nn >> 1)) * 32 + lane) * 4
                              + ((nn & 1) << 1);
                int row = m0 + wm * 32 + mt * 16 + (lane >> 2);
                float sn, cs;
                sincosf((float)row * inv, &sn, &cs);
                uint32_t hh, ll;
                bsplit((v0 * cs - v1 * sn) * 0.125f, (v0 * sn + v1 * cs) * 0.125f, hh, ll);
                gQh[base] = hh; gQl[base] = ll;
                sincosf((float)(row + 8) * inv, &sn, &cs);
                bsplit((v2 * cs - v3 * sn) * 0.125f, (v2 * sn + v3 * cs) * 0.125f, hh, ll);
                gQh[base + 1] = hh; gQl[base + 1] = ll;
            } else if (mode == 2) {          // K: RoPE -> attn B-frag
                int kvh2 = (bx - 8) * 2 + (nglob >> 3);
                int fidx = (nn * 4 + (lane & 3)) & 15;
                float inv = exp2f(-(float)fidx * L2T16);
                uint32_t kb = (uint32_t)(kvh2 * 32 + mb) << 11;
                int sK = nn >> 1;
                int row = m0 + wm * 32 + mt * 16 + (lane >> 2);
                float sn, cs;
                sincosf((float)row * inv, &sn, &cs);
                uint32_t hh, ll;
                int kt8 = wm * 4 + mt * 2;
                bsplit(v0 * cs - v1 * sn, v0 * sn + v1 * cs, hh, ll);
                uint32_t i0 = kb + (((sK * 8 + kt8) * 32 + lane) << 1) + (nn & 1);
                gKh[i0] = hh; gKl[i0] = ll;
                sincosf((float)(row + 8) * inv, &sn, &cs);
                bsplit(v2 * cs - v3 * sn, v2 * sn + v3 * cs, hh, ll);
                uint32_t i1 = kb + (((sK * 8 + kt8 + 1) * 32 + lane) << 1) + (nn & 1);
                gKh[i1] = hh; gKl[i1] = ll;
            } else {                         // V: pair rows via shfl -> attn B-frag
                int kvh2 = (bx - 10) * 2 + (nglob >> 3);
                float b0 = __shfl_xor_sync(0xffffffffu, v0, 4);
                float b1 = __shfl_xor_sync(0xffffffffu, v1, 4);
                float b2 = __shfl_xor_sync(0xffffffffu, v2, 4);
                float b3 = __shfl_xor_sync(0xffffffffu, v3, 4);
                if (!(lane & 4)) {
                    uint32_t vb = (uint32_t)(kvh2 * 32 + mb) << 11;
                    #pragma unroll
                    for (int grp = 0; grp < 2; grp++) {
                        int kp = wm * 16 + mt * 8 + grp * 4 + (lane >> 3);
                        int sv = kp >> 3, cv = kp & 3, rgv = (kp >> 2) & 1;
                        #pragma unroll
                        for (int colsel = 0; colsel < 2; colsel++) {
                            float x0 = grp ? (colsel ? v3 : v2) : (colsel ? v1 : v0);
                            float x1 = grp ? (colsel ? b3 : b2) : (colsel ? b1 : b0);
                            int d7 = (lane & 3) * 2 + colsel;
                            uint32_t idx = vb + ((((sv * 8 + nn) << 5)
                                         + ((d7 << 2) | cv)) << 1) + rgv;
                            uint32_t hh, ll;
                            bsplit(x0, x1, hh, ll);
                            gVh[idx] = hh; gVl[idx] = ll;
                        }
                    }
                }
            }
        }
    }
}

// ================= MMA flash attention (bf16 3x, causal, GQA 4:1) ============
// Block = 128 threads (4 warps) = 64 q rows of one head.
// K/V tiles staged by pure cp.async copy of fragment-ordered globals.
// SMEM: 2 bufs x [Kh 2048 | Kl 2048 | Vh 2048 | Vl 2048] u32 = 64 KB.
#define ATT_SMEM (2 * 8192 * 4)

__global__ __launch_bounds__(128, 3) void attn_frag_kernel()
{
    extern __shared__ uint32_t sm[];
    const uint32_t sb = (uint32_t)__cvta_generic_to_shared(sm);
    const int tid  = threadIdx.x;
    const int wid  = tid >> 5;
    const int lane = tid & 31;

    const int h   = blockIdx.y;
    const int qt  = gridDim.x - 1 - blockIdx.x;   // heavy tiles first
    const int q0  = qt * 64;
    const int kvh = h >> 2;

    // ---- Q fragments ----
    uint32_t qh[4][4], ql[4][4];
    {
        const uint32_t* Qb = gQh + ((size_t)(h * 32 + qt) << 11);
        const uint32_t* Qb2 = gQl + ((size_t)(h * 32 + qt) << 11);
        #pragma unroll
        for (int s = 0; s < 4; s++) {
            *(uint4*)qh[s] = *(const uint4*)&Qb[((wid * 4 + s) * 32 + lane) * 4];
            *(uint4*)ql[s] = *(const uint4*)&Qb2[((wid * 4 + s) * 32 + lane) * 4];
        }
    }

    const int r0 = q0 + wid * 16 + (lane >> 2);
    const int r1 = r0 + 8;
    const int c2 = (lane & 3) * 2;

    float m0 = -1e30f, m1 = -1e30f, l0 = 0.f, l1 = 0.f;
    float o[8][4];
    #pragma unroll
    for (int nt = 0; nt < 8; nt++)
        #pragma unroll
        for (int v = 0; v < 4; v++) o[nt][v] = 0.f;

    auto issue = [&](int t, int buf) {
        uint32_t db = sb + buf * 8192 * 4;
        const uint32_t* kh = gKh + ((size_t)(kvh * 32 + t) << 11);
        const uint32_t* kl = gKl + ((size_t)(kvh * 32 + t) << 11);
        const uint32_t* vh = gVh + ((size_t)(kvh * 32 + t) << 11);
        const uint32_t* vl = gVl + ((size_t)(kvh * 32 + t) << 11);
        #pragma unroll
        for (int i = 0; i < 4; i++) {
            int j = tid + i * 128;
            cp16(db + j * 16,          kh + j * 4);
            cp16(db + 8192 + j * 16,   kl + j * 4);
            cp16(db + 16384 + j * 16,  vh + j * 4);
            cp16(db + 24576 + j * 16,  vl + j * 4);
        }
    };

    issue(0, 0); CP_COMMIT;
    for (int t = 0; t <= qt; t++) {
        if (t < qt) { issue(t + 1, (t + 1) & 1); CP_COMMIT; }
        if (t < qt) { CP_WAIT1; } else { CP_WAIT0; }
        __syncthreads();

        const uint32_t* Kh = sm + (t & 1) * 8192;
        const uint32_t* Kl = Kh + 2048;
        const uint32_t* Vh = Kh + 4096;
        const uint32_t* Vl = Kh + 6144;
        const int kv0 = t * 64;

        // ---- S = Q K^T (3xBF16, pass-major) ----
        float s_[8][4];
        #pragma unroll
        for (int nt = 0; nt < 8; nt++)
            #pragma unroll
            for (int v = 0; v < 4; v++) s_[nt][v] = 0.f;
        #pragma unroll
        for (int s = 0; s < 4; s++) {
            #pragma unroll
            for (int ntb = 0; ntb < 2; ntb++) {
                uint32_t k_h[4][2], k_l[4][2];
                #pragma unroll
                for (int j = 0; j < 4; j++) {
                    int nt = ntb * 4 + j;
                    *(uint2*)k_h[j] = *(const uint2*)&Kh[((s * 8 + nt) * 32 + lane) * 2];
                    *(uint2*)k_l[j] = *(const uint2*)&Kl[((s * 8 + nt) * 32 + lane) * 2];
                }
                #pragma unroll
                for (int j = 0; j < 4; j++) mma16(s_[ntb * 4 + j], qh[s], k_h[j]);
                #pragma unroll
                for (int j = 0; j < 4; j++) mma16(s_[ntb * 4 + j], qh[s], k_l[j]);
                #pragma unroll
                for (int j = 0; j < 4; j++) mma16(s_[ntb * 4 + j], ql[s], k_h[j]);
            }
        }

        if (t == qt) {
            #pragma unroll
            for (int nt = 0; nt < 8; nt++) {
                int cb = kv0 + nt * 8 + c2;
                if (cb > r0)     s_[nt][0] = -1e30f;
                if (cb + 1 > r0) s_[nt][1] = -1e30f;
                if (cb > r1)     s_[nt][2] = -1e30f;
                if (cb + 1 > r1) s_[nt][3] = -1e30f;
            }
        }

        // ---- online softmax ----
        float tm0 = -1e30f, tm1 = -1e30f;
        #pragma unroll
        for (int nt = 0; nt < 8; nt++) {
            tm0 = fmaxf(tm0, fmaxf(s_[nt][0], s_[nt][1]));
            tm1 = fmaxf(tm1, fmaxf(s_[nt][2], s_[nt][3]));
        }
        tm0 = fmaxf(tm0, __shfl_xor_sync(0xffffffffu, tm0, 1));
        tm0 = fmaxf(tm0, __shfl_xor_sync(0xffffffffu, tm0, 2));
        tm1 = fmaxf(tm1, __shfl_xor_sync(0xffffffffu, tm1, 1));
        tm1 = fmaxf(tm1, __shfl_xor_sync(0xffffffffu, tm1, 2));
        float mn0 = fmaxf(m0, tm0), mn1 = fmaxf(m1, tm1);
        float f0 = __expf(m0 - mn0), f1 = __expf(m1 - mn1);
        m0 = mn0; m1 = mn1;
        float rs0 = 0.f, rs1 = 0.f;
        #pragma unroll
        for (int nt = 0; nt < 8; nt++) {
            s_[nt][0] = __expf(s_[nt][0] - mn0); rs0 += s_[nt][0];
            s_[nt][1] = __expf(s_[nt][1] - mn0); rs0 += s_[nt][1];
            s_[nt][2] = __expf(s_[nt][2] - mn1); rs1 += s_[nt][2];
            s_[nt][3] = __expf(s_[nt][3] - mn1); rs1 += s_[nt][3];
        }
        rs0 += __shfl_xor_sync(0xffffffffu, rs0, 1);
        rs0 += __shfl_xor_sync(0xffffffffu, rs0, 2);
        rs1 += __shfl_xor_sync(0xffffffffu, rs1, 1);
        rs1 += __shfl_xor_sync(0xffffffffu, rs1, 2);
        l0 = l0 * f0 + rs0;
        l1 = l1 * f1 + rs1;
        #pragma unroll
        for (int nt = 0; nt < 8; nt++) {
            o[nt][0] *= f0; o[nt][1] *= f0;
            o[nt][2] *= f1; o[nt][3] *= f1;
        }

        // ---- O += P V ----
        #pragma unroll
        for (int s = 0; s < 4; s++) {
            uint32_t ph[4], pl[4];
            bsplit(s_[2 * s][0],     s_[2 * s][1],     ph[0], pl[0]);
            bsplit(s_[2 * s][2],     s_[2 * s][3],     ph[1], pl[1]);
            bsplit(s_[2 * s + 1][0], s_[2 * s + 1][1], ph[2], pl[2]);
            bsplit(s_[2 * s + 1][2], s_[2 * s + 1][3], ph[3], pl[3]);
            #pragma unroll
            for (int ntb = 0; ntb < 2; ntb++) {
                uint32_t v_h[4][2], v_l[4][2];
                #pragma unroll
                for (int j = 0; j < 4; j++) {
                    int nt = ntb * 4 + j;
                    *(uint2*)v_h[j] = *(const uint2*)&Vh[((s * 8 + nt) * 32 + lane) * 2];
                    *(uint2*)v_l[j] = *(const uint2*)&Vl[((s * 8 + nt) * 32 + lane) * 2];
                }
                #pragma unroll
                for (int j = 0; j < 4; j++) mma16(o[ntb * 4 + j], ph, v_h[j]);
                #pragma unroll
                for (int j = 0; j < 4; j++) mma16(o[ntb * 4 + j], ph, v_l[j]);
                #pragma unroll
                for (int j = 0; j < 4; j++) mma16(o[ntb * 4 + j], pl, v_h[j]);
            }
        }
        __syncthreads();
    }

    // ---- epilogue: write A-fragment hi/lo for the out-projection ----
    float il0 = 1.0f / l0, il1 = 1.0f / l1;
    #pragma unroll
    for (int nt = 0; nt < 8; nt++) {
        int chA = h * 2 + (nt >> 2);
        int sA  = (nt & 3) >> 1;
        uint32_t base = ((uint32_t)(qt * 32 + chA) << 10)
                      + ((sA * 4 + wid) * 32 + lane) * 4 + ((nt & 1) << 1);
        uint32_t hh, ll;
        bsplit(o[nt][0] * il0, o[nt][1] * il0, hh, ll);
        gAh[base] = hh; gAl[base] = ll;
        bsplit(o[nt][2] * il1, o[nt][3] * il1, hh, ll);
        gAh[base + 1] = hh; gAl[base + 1] = ll;
    }
}

// ---------------- launch ----------------------------------------------------
extern "C" void kernel_launch(void* const* d_in, const int* in_sizes, int n_in,
                              void* d_out, int out_size)
{
    const float* X  = (const float*)d_in[0];
    const float* Wq = (const float*)d_in[1];
    const float* Wk = (const float*)d_in[2];
    const float* Wv = (const float*)d_in[3];
    const float* Wo = (const float*)d_in[4];
    float* out = (float*)d_out;

    uint32_t *pXh, *pXl, *pWh, *pWl, *pWoh, *pWol, *pAh, *pAl;
    cudaGetSymbolAddress((void**)&pXh, gXh);
    cudaGetSymbolAddress((void**)&pXl, gXl);
    cudaGetSymbolAddress((void**)&pWh, gWh);
    cudaGetSymbolAddress((void**)&pWl, gWl);
    cudaGetSymbolAddress((void**)&pWoh, gWoh);
    cudaGetSymbolAddress((void**)&pWol, gWol);
    cudaGetSymbolAddress((void**)&pAh, gAh);
    cudaGetSymbolAddress((void**)&pAl, gAl);

    cudaFuncSetAttribute(gemm_frag_kernel,
                         cudaFuncAttributeMaxDynamicSharedMemorySize, GEMM_SMEM);
    cudaFuncSetAttribute(attn_frag_kernel,
                         cudaFuncAttributeMaxDynamicSharedMemorySize, ATT_SMEM);

    // Conversions
    convA_kernel<<<2048, 512>>>(X, pXh, pXl);
    convW_kernel<<<1024, 512>>>(Wq, 1024, pWh, pWl, 0);
    convW_kernel<<<256, 512>>>(Wk, 256, pWh, pWl, 8);
    convW_kernel<<<256, 512>>>(Wv, 256, pWh, pWl, 10);
    convW_kernel<<<1024, 512>>>(Wo, 1024, pWoh, pWol, 0);

    // Merged QKV (modes: bx<8 Q+RoPE, bx 8-9 K+RoPE, bx 10-11 V)
    gemm_frag_kernel<<<dim3(12, 32), 128, GEMM_SMEM>>>(pXh, pXl, pWh, pWl, nullptr, 1);

    // Flash attention (reads/writes fragment-ordered globals)
    attn_frag_kernel<<<dim3(32, NH), 128, ATT_SMEM>>>();

    // Output projection (mode 0: plain fp32 store)
    gemm_frag_kernel<<<dim3(8, 32), 128, GEMM_SMEM>>>(pAh, pAl, pWoh, pWol, out, 0);
}

// round 10
// speedup vs baseline: 6.4393x; 1.0008x over previous
#include <cuda_runtime.h>
#include <cuda_bf16.h>
#include <math.h>
#include <stdint.h>

// Problem constants
#define S    2048
#define HID  1024
#define NH   16
#define NKV  4
#define HD   64

// ---------------- fragment-ordered scratch (device globals) -----------------
// A-fragment chunk (64 rows x 32 k, 1024 u32): idx = ((s*4+mt)*32+lane)*4+rg
// B-fragment chunk (128 cols x 32 k, 2048 u32): idx = ((s*16+nt)*32+lane)*2+rg
__device__ uint32_t gXh[32 * 32 * 1024], gXl[32 * 32 * 1024];   // X A-frag
__device__ uint32_t gWh[12 * 32 * 2048], gWl[12 * 32 * 2048];   // Wq|Wk|Wv B-frag
__device__ uint32_t gWoh[8 * 32 * 2048], gWol[8 * 32 * 2048];   // Wo B-frag
__device__ uint32_t gQh[16 * 32 * 2048], gQl[16 * 32 * 2048];   // Q attn A-frag
__device__ uint32_t gKh[4 * 32 * 2048],  gKl[4 * 32 * 2048];    // K attn B-frag
__device__ uint32_t gVh[4 * 32 * 2048],  gVl[4 * 32 * 2048];    // V attn B-frag
__device__ uint32_t gAh[32 * 32 * 1024], gAl[32 * 32 * 1024];   // attn out A-frag

// ---------------- helpers ----------------------------------------------------
__device__ __forceinline__ void bsplit(float x, float y, uint32_t& hi, uint32_t& lo) {
    __nv_bfloat162 h = __floats2bfloat162_rn(x, y);
    float hx = __bfloat162float(h.x);
    float hy = __bfloat162float(h.y);
    __nv_bfloat162 l = __floats2bfloat162_rn(x - hx, y - hy);
    hi = *(uint32_t*)&h;
    lo = *(uint32_t*)&l;
}

__device__ __forceinline__ void mma16(float* d, const uint32_t* a, const uint32_t* b) {
    asm volatile(
        "mma.sync.aligned.m16n8k16.row.col.f32.bf16.bf16.f32 "
        "{%0,%1,%2,%3}, {%4,%5,%6,%7}, {%8,%9}, {%0,%1,%2,%3};"
        : "+f"(d[0]), "+f"(d[1]), "+f"(d[2]), "+f"(d[3])
        : "r"(a[0]), "r"(a[1]), "r"(a[2]), "r"(a[3]), "r"(b[0]), "r"(b[1]));
}

__device__ __forceinline__ void cp16(uint32_t saddr, const void* g) {
    asm volatile("cp.async.cg.shared.global [%0], [%1], 16;" :: "r"(saddr), "l"(g));
}
#define CP_COMMIT asm volatile("cp.async.commit_group;" ::: "memory")
#define CP_WAIT0  asm volatile("cp.async.wait_group 0;" ::: "memory")
#define CP_WAIT1  asm volatile("cp.async.wait_group 1;" ::: "memory")

#define L2T16 (13.287712379549449f / 16.0f)   // log2(10000)/16

// ================= merged gather-style conversion kernel =====================
// Output-indexed (coalesced stores), source gathered through L2.
// bx ranges: [0,1024) X->A-frag; [1024,2048) Wq; [2048,2304) Wk;
//            [2304,2560) Wv; [2560,3584) Wo.
__global__ __launch_bounds__(256) void convAll_kernel(
    const float* __restrict__ X,
    const float* __restrict__ Wq, const float* __restrict__ Wk,
    const float* __restrict__ Wv, const float* __restrict__ Wo)
{
    const int bx = blockIdx.x;
    const int tid = threadIdx.x;

    if (bx < 1024) {
        // ---- X -> A-frag: thread produces 4 consecutive u32 (rg 0..3) ----
        int t = bx * 256 + tid;          // [0, 262144)
        int chunkg = t >> 8;             // mb*32 + ch
        int fr = t & 255;                // (s*4+mt)*32 + ln
        int ln = fr & 31, smt = fr >> 5;
        int s = smt >> 2, mt = smt & 3;
        int mb = chunkg >> 5, ch = chunkg & 31;
        int c = ln & 3, r8 = ln >> 2;
        int rowA = mb * 64 + mt * 16 + r8;
        int kb = ch * 32 + s * 16 + c * 2;

        float2 v0 = *(const float2*)(X + (size_t)rowA * HID + kb);
        float2 v1 = *(const float2*)(X + (size_t)(rowA + 8) * HID + kb);
        float2 v2 = *(const float2*)(X + (size_t)rowA * HID + kb + 8);
        float2 v3 = *(const float2*)(X + (size_t)(rowA + 8) * HID + kb + 8);
        uint4 H, L;
        bsplit(v0.x, v0.y, H.x, L.x);
        bsplit(v1.x, v1.y, H.y, L.y);
        bsplit(v2.x, v2.y, H.z, L.z);
        bsplit(v3.x, v3.y, H.w, L.w);
        *(uint4*)&gXh[((size_t)chunkg << 10) + fr * 4] = H;
        *(uint4*)&gXl[((size_t)chunkg << 10) + fr * 4] = L;
    } else {
        // ---- W -> B-frag: thread produces 2 consecutive u32 (rg 0..1) ----
        const float* W; uint32_t *Gh, *Gl; int N, nb_base, t;
        if (bx < 2048)      { W = Wq; N = 1024; nb_base = 0;  t = (bx - 1024) * 256 + tid;
                              Gh = gWh;  Gl = gWl; }
        else if (bx < 2304) { W = Wk; N = 256;  nb_base = 8;  t = (bx - 2048) * 256 + tid;
                              Gh = gWh;  Gl = gWl; }
        else if (bx < 2560) { W = Wv; N = 256;  nb_base = 10; t = (bx - 2304) * 256 + tid;
                              Gh = gWh;  Gl = gWl; }
        else                { W = Wo; N = 1024; nb_base = 0;  t = (bx - 2560) * 256 + tid;
                              Gh = gWoh; Gl = gWol; }
        int chunkg = t >> 10;            // nb*32 + ch
        int fr = t & 1023;               // (s*16+nt)*32 + ln
        int ln = fr & 31, snt = fr >> 5;
        int s = snt >> 4, nt = snt & 15;
        int nb = chunkg >> 5, ch = chunkg & 31;
        int c = ln & 3, nn7 = ln >> 2;
        int n = nb * 128 + nt * 8 + nn7;
        int k0 = ch * 32 + s * 16 + c * 2;     // rg=0
        int k1 = k0 + 8;                       // rg=1

        float a0 = W[(size_t)k0 * N + n];
        float a1 = W[(size_t)(k0 + 1) * N + n];
        float b0 = W[(size_t)k1 * N + n];
        float b1 = W[(size_t)(k1 + 1) * N + n];
        uint2 H, L;
        bsplit(a0, a1, H.x, L.x);
        bsplit(b0, b1, H.y, L.y);
        size_t base = ((size_t)((nb_base + nb) * 32 + ch) << 11) + fr * 2;
        *(uint2*)&Gh[base] = H;
        *(uint2*)&Gl[base] = L;
    }
}

// ================= fragment GEMM (3xBF16, M=128 tile, cp.async) ==============
// Block: 128(M) x 128(N), BK=32, 256 threads = 8 warps (4 M x 2 N).
// SMEM buffer (u32): Ah0|Ah1[2048] Al0|Al1[2048] Bh[2048] Bl[2048] = 8192 = 32KB.
#define GEMM_SMEM (2 * 8192 * 4)

__global__ __launch_bounds__(256, 2) void gemm_frag_kernel(
    const uint32_t* __restrict__ Agh, const uint32_t* __restrict__ Agl,
    const uint32_t* __restrict__ Wgh, const uint32_t* __restrict__ Wgl,
    float* __restrict__ Cout, int qkv)
{
    extern __shared__ uint32_t sm[];
    const uint32_t sb = (uint32_t)__cvta_generic_to_shared(sm);
    const int tid  = threadIdx.x;
    const int wid  = tid >> 5;
    const int lane = tid & 31;
    const int wm   = wid & 3;      // 0..3 over M=128
    const int wn   = wid >> 2;     // 0..1 over N=128
    const int by   = blockIdx.y;
    const int bx   = blockIdx.x;
    const int mbs  = wm >> 1;            // 64-row sub-block select
    const int mtb  = (wm & 1) * 2;       // 16-row tile base within sub-block

    const uint32_t* Ah0 = Agh + ((size_t)(2 * by) << 15);
    const uint32_t* Ah1 = Agh + ((size_t)(2 * by + 1) << 15);
    const uint32_t* Al0 = Agl + ((size_t)(2 * by) << 15);
    const uint32_t* Al1 = Agl + ((size_t)(2 * by + 1) << 15);
    const uint32_t* Bh_src = Wgh + ((size_t)bx << 16);
    const uint32_t* Bl_src = Wgl + ((size_t)bx << 16);

    float acc[2][8][4];
    #pragma unroll
    for (int i = 0; i < 2; i++)
        #pragma unroll
        for (int j = 0; j < 8; j++)
            #pragma unroll
            for (int v = 0; v < 4; v++) acc[i][j][v] = 0.f;

    auto issue = [&](int ch, int buf) {
        uint32_t db = sb + buf * 8192 * 4;
        #pragma unroll
        for (int i = 0; i < 2; i++) {
            int j = tid + i * 256;             // 0..511
            int ms = j >> 8;
            int off = (j & 255) * 4;
            cp16(db + j * 16,         (ms ? Ah1 : Ah0) + (ch << 10) + off);
            cp16(db + 8192 + j * 16,  (ms ? Al1 : Al0) + (ch << 10) + off);
            cp16(db + 16384 + j * 16, Bh_src + (ch << 11) + j * 4);
            cp16(db + 24576 + j * 16, Bl_src + (ch << 11) + j * 4);
        }
    };
    auto compute = [&](int buf) {
        const uint32_t* Ah = sm + buf * 8192 + mbs * 1024;
        const uint32_t* Al = Ah + 2048;
        const uint32_t* Bh = sm + buf * 8192 + 4096;
        const uint32_t* Bl = Bh + 2048;
        #pragma unroll
        for (int s = 0; s < 2; s++) {
            uint32_t a_h[2][4], a_l[2][4];
            #pragma unroll
            for (int mt = 0; mt < 2; mt++) {
                *(uint4*)a_h[mt] = *(const uint4*)&Ah[((s * 4 + mtb + mt) * 32 + lane) * 4];
                *(uint4*)a_l[mt] = *(const uint4*)&Al[((s * 4 + mtb + mt) * 32 + lane) * 4];
            }
            #pragma unroll
            for (int ntb = 0; ntb < 2; ntb++) {
                uint32_t b_h[4][2], b_l[4][2];
                #pragma unroll
                for (int j = 0; j < 4; j++) {
                    int nt = wn * 8 + ntb * 4 + j;
                    *(uint2*)b_h[j] = *(const uint2*)&Bh[((s * 16 + nt) * 32 + lane) * 2];
                    *(uint2*)b_l[j] = *(const uint2*)&Bl[((s * 16 + nt) * 32 + lane) * 2];
                }
                #pragma unroll
                for (int j = 0; j < 4; j++)
                    #pragma unroll
                    for (int mt = 0; mt < 2; mt++) {
                        mma16(acc[mt][ntb * 4 + j], a_h[mt], b_h[j]);
                        mma16(acc[mt][ntb * 4 + j], a_h[mt], b_l[j]);
                        mma16(acc[mt][ntb * 4 + j], a_l[mt], b_h[j]);
                    }
            }
        }
    };

    issue(0, 0); CP_COMMIT;
    for (int ch = 0; ch < 32; ch++) {
        if (ch < 31) { issue(ch + 1, (ch + 1) & 1); CP_COMMIT; }
        if (ch < 31) { CP_WAIT1; } else { CP_WAIT0; }
        __syncthreads();
        compute(ch & 1);
        __syncthreads();
    }

    // ---- epilogue ----
    const int mode = qkv ? (bx < 8 ? 1 : (bx < 10 ? 2 : 3)) : 0;

    #pragma unroll
    for (int mt = 0; mt < 2; mt++) {
        const int tile16 = mtb + mt;                 // 16-row tile in 64-row blk
        const int mb = 2 * by + mbs;                 // 64-row block index
        const int row = mb * 64 + tile16 * 16 + (lane >> 2);
        #pragma unroll
        for (int nt = 0; nt < 8; nt++) {
            const int nglob = wn * 8 + nt;
            const int nn = nglob & 7;
            float v0 = acc[mt][nt][0], v1 = acc[mt][nt][1];
            float v2 = acc[mt][nt][2], v3 = acc[mt][nt][3];

            if (mode == 0) {
                int col = bx * 128 + nglob * 8 + (lane & 3) * 2;
                *(float2*)(Cout + (size_t)row * HID + col) = make_float2(v0, v1);
                *(float2*)(Cout + (size_t)(row + 8) * HID + col) = make_float2(v2, v3);
            } else if (mode == 1) {          // Q: RoPE + 1/8 -> attn A-frag
                int h2 = bx * 2 + (nglob >> 3);
                int fidx = (nn * 4 + (lane & 3)) & 15;
                float inv = exp2f(-(float)fidx * L2T16);
                uint32_t base = ((uint32_t)(h2 * 32 + mb) << 11)
                              + ((tile16 * 4 + (nn >> 1)) * 32 + lane) * 4
                              + ((nn & 1) << 1);
                float sn, cs;
                sincosf((float)row * inv, &sn, &cs);
                uint32_t hh, ll;
                bsplit((v0 * cs - v1 * sn) * 0.125f, (v0 * sn + v1 * cs) * 0.125f, hh, ll);
                gQh[base] = hh; gQl[base] = ll;
                sincosf((float)(row + 8) * inv, &sn, &cs);
                bsplit((v2 * cs - v3 * sn) * 0.125f, (v2 * sn + v3 * cs) * 0.125f, hh, ll);
                gQh[base + 1] = hh; gQl[base + 1] = ll;
            } else if (mode == 2) {          // K: RoPE -> attn B-frag
                int kvh2 = (bx - 8) * 2 + (nglob >> 3);
                int fidx = (nn * 4 + (lane & 3)) & 15;
                float inv = exp2f(-(float)fidx * L2T16);
                uint32_t kb = (uint32_t)(kvh2 * 32 + mb) << 11;
                int sK = nn >> 1;
                int kt8 = tile16 * 2;
                float sn, cs;
                sincosf((float)row * inv, &sn, &cs);
                uint32_t hh, ll;
                bsplit(v0 * cs - v1 * sn, v0 * sn + v1 * cs, hh, ll);
                uint32_t i0 = kb + (((sK * 8 + kt8) * 32 + lane) << 1) + (nn & 1);
                gKh[i0] = hh; gKl[i0] = ll;
                sincosf((float)(row + 8) * inv, &sn, &cs);
                bsplit(v2 * cs - v3 * sn, v2 * sn + v3 * cs, hh, ll);
                uint32_t i1 = kb + (((sK * 8 + kt8 + 1) * 32 + lane) << 1) + (nn & 1);
                gKh[i1] = hh; gKl[i1] = ll;
            } else {                         // V: pair rows via shfl -> attn B-frag
                int kvh2 = (bx - 10) * 2 + (nglob >> 3);
                float b0 = __shfl_xor_sync(0xffffffffu, v0, 4);
                float b1 = __shfl_xor_sync(0xffffffffu, v1, 4);
                float b2 = __shfl_xor_sync(0xffffffffu, v2, 4);
                float b3 = __shfl_xor_sync(0xffffffffu, v3, 4);
                if (!(lane & 4)) {
                    uint32_t vb = (uint32_t)(kvh2 * 32 + mb) << 11;
                    #pragma unroll
                    for (int grp = 0; grp < 2; grp++) {
                        int kp = tile16 * 8 + grp * 4 + (lane >> 3);
                        int sv = kp >> 3, cv = kp & 3, rgv = (kp >> 2) & 1;
                        #pragma unroll
                        for (int colsel = 0; colsel < 2; colsel++) {
                            float x0 = grp ? (colsel ? v3 : v2) : (colsel ? v1 : v0);
                            float x1 = grp ? (colsel ? b3 : b2) : (colsel ? b1 : b0);
                            int d7 = (lane & 3) * 2 + colsel;
                            uint32_t idx = vb + ((((sv * 8 + nn) << 5)
                                         + ((d7 << 2) | cv)) << 1) + rgv;
                            uint32_t hh, ll;
                            bsplit(x0, x1, hh, ll);
                            gVh[idx] = hh; gVl[idx] = ll;
                        }
                    }
                }
            }
        }
    }
}

// ================= MMA flash attention (bf16 3x, causal, GQA 4:1) ============
#define ATT_SMEM (2 * 8192 * 4)

__global__ __launch_bounds__(128, 3) void attn_frag_kernel()
{
    extern __shared__ uint32_t sm[];
    const uint32_t sb = (uint32_t)__cvta_generic_to_shared(sm);
    const int tid  = threadIdx.x;
    const int wid  = tid >> 5;
    const int lane = tid & 31;

    const int h   = blockIdx.y;
    const int qt  = gridDim.x - 1 - blockIdx.x;   // heavy tiles first
    const int q0  = qt * 64;
    const int kvh = h >> 2;

    uint32_t qh[4][4], ql[4][4];
    {
        const uint32_t* Qb = gQh + ((size_t)(h * 32 + qt) << 11);
        const uint32_t* Qb2 = gQl + ((size_t)(h * 32 + qt) << 11);
        #pragma unroll
        for (int s = 0; s < 4; s++) {
            *(uint4*)qh[s] = *(const uint4*)&Qb[((wid * 4 + s) * 32 + lane) * 4];
            *(uint4*)ql[s] = *(const uint4*)&Qb2[((wid * 4 + s) * 32 + lane) * 4];
        }
    }

    const int r0 = q0 + wid * 16 + (lane >> 2);
    const int r1 = r0 + 8;
    const int c2 = (lane & 3) * 2;

    float m0 = -1e30f, m1 = -1e30f, l0 = 0.f, l1 = 0.f;
    float o[8][4];
    #pragma unroll
    for (int nt = 0; nt < 8; nt++)
        #pragma unroll
        for (int v = 0; v < 4; v++) o[nt][v] = 0.f;

    auto issue = [&](int t, int buf) {
        uint32_t db = sb + buf * 8192 * 4;
        const uint32_t* kh = gKh + ((size_t)(kvh * 32 + t) << 11);
        const uint32_t* kl = gKl + ((size_t)(kvh * 32 + t) << 11);
        const uint32_t* vh = gVh + ((size_t)(kvh * 32 + t) << 11);
        const uint32_t* vl = gVl + ((size_t)(kvh * 32 + t) << 11);
        #pragma unroll
        for (int i = 0; i < 4; i++) {
            int j = tid + i * 128;
            cp16(db + j * 16,          kh + j * 4);
            cp16(db + 8192 + j * 16,   kl + j * 4);
            cp16(db + 16384 + j * 16,  vh + j * 4);
            cp16(db + 24576 + j * 16,  vl + j * 4);
        }
    };

    issue(0, 0); CP_COMMIT;
    for (int t = 0; t <= qt; t++) {
        if (t < qt) { issue(t + 1, (t + 1) & 1); CP_COMMIT; }
        if (t < qt) { CP_WAIT1; } else { CP_WAIT0; }
        __syncthreads();

        const uint32_t* Kh = sm + (t & 1) * 8192;
        const uint32_t* Kl = Kh + 2048;
        const uint32_t* Vh = Kh + 4096;
        const uint32_t* Vl = Kh + 6144;
        const int kv0 = t * 64;

        float s_[8][4];
        #pragma unroll
        for (int nt = 0; nt < 8; nt++)
            #pragma unroll
            for (int v = 0; v < 4; v++) s_[nt][v] = 0.f;
        #pragma unroll
        for (int s = 0; s < 4; s++) {
            #pragma unroll
            for (int ntb = 0; ntb < 2; ntb++) {
                uint32_t k_h[4][2], k_l[4][2];
                #pragma unroll
                for (int j = 0; j < 4; j++) {
                    int nt = ntb * 4 + j;
                    *(uint2*)k_h[j] = *(const uint2*)&Kh[((s * 8 + nt) * 32 + lane) * 2];
                    *(uint2*)k_l[j] = *(const uint2*)&Kl[((s * 8 + nt) * 32 + lane) * 2];
                }
                #pragma unroll
                for (int j = 0; j < 4; j++) mma16(s_[ntb * 4 + j], qh[s], k_h[j]);
                #pragma unroll
                for (int j = 0; j < 4; j++) mma16(s_[ntb * 4 + j], qh[s], k_l[j]);
                #pragma unroll
                for (int j = 0; j < 4; j++) mma16(s_[ntb * 4 + j], ql[s], k_h[j]);
            }
        }

        if (t == qt) {
            #pragma unroll
            for (int nt = 0; nt < 8; nt++) {
                int cb = kv0 + nt * 8 + c2;
                if (cb > r0)     s_[nt][0] = -1e30f;
                if (cb + 1 > r0) s_[nt][1] = -1e30f;
                if (cb > r1)     s_[nt][2] = -1e30f;
                if (cb + 1 > r1) s_[nt][3] = -1e30f;
            }
        }

        float tm0 = -1e30f, tm1 = -1e30f;
        #pragma unroll
        for (int nt = 0; nt < 8; nt++) {
            tm0 = fmaxf(tm0, fmaxf(s_[nt][0], s_[nt][1]));
            tm1 = fmaxf(tm1, fmaxf(s_[nt][2], s_[nt][3]));
        }
        tm0 = fmaxf(tm0, __shfl_xor_sync(0xffffffffu, tm0, 1));
        tm0 = fmaxf(tm0, __shfl_xor_sync(0xffffffffu, tm0, 2));
        tm1 = fmaxf(tm1, __shfl_xor_sync(0xffffffffu, tm1, 1));
        tm1 = fmaxf(tm1, __shfl_xor_sync(0xffffffffu, tm1, 2));
        float mn0 = fmaxf(m0, tm0), mn1 = fmaxf(m1, tm1);
        float f0 = __expf(m0 - mn0), f1 = __expf(m1 - mn1);
        m0 = mn0; m1 = mn1;
        float rs0 = 0.f, rs1 = 0.f;
        #pragma unroll
        for (int nt = 0; nt < 8; nt++) {
            s_[nt][0] = __expf(s_[nt][0] - mn0); rs0 += s_[nt][0];
            s_[nt][1] = __expf(s_[nt][1] - mn0); rs0 += s_[nt][1];
            s_[nt][2] = __expf(s_[nt][2] - mn1); rs1 += s_[nt][2];
            s_[nt][3] = __expf(s_[nt][3] - mn1); rs1 += s_[nt][3];
        }
        rs0 += __shfl_xor_sync(0xffffffffu, rs0, 1);
        rs0 += __shfl_xor_sync(0xffffffffu, rs0, 2);
        rs1 += __shfl_xor_sync(0xffffffffu, rs1, 1);
        rs1 += __shfl_xor_sync(0xffffffffu, rs1, 2);
        l0 = l0 * f0 + rs0;
        l1 = l1 * f1 + rs1;
        #pragma unroll
        for (int nt = 0; nt < 8; nt++) {
            o[nt][0] *= f0; o[nt][1] *= f0;
            o[nt][2] *= f1; o[nt][3] *= f1;
        }

        #pragma unroll
        for (int s = 0; s < 4; s++) {
            uint32_t ph[4], pl[4];
            bsplit(s_[2 * s][0],     s_[2 * s][1],     ph[0], pl[0]);
            bsplit(s_[2 * s][2],     s_[2 * s][3],     ph[1], pl[1]);
            bsplit(s_[2 * s + 1][0], s_[2 * s + 1][1], ph[2], pl[2]);
            bsplit(s_[2 * s + 1][2], s_[2 * s + 1][3], ph[3], pl[3]);
            #pragma unroll
            for (int ntb = 0; ntb < 2; ntb++) {
                uint32_t v_h[4][2], v_l[4][2];
                #pragma unroll
                for (int j = 0; j < 4; j++) {
                    int nt = ntb * 4 + j;
                    *(uint2*)v_h[j] = *(const uint2*)&Vh[((s * 8 + nt) * 32 + lane) * 2];
                    *(uint2*)v_l[j] = *(const uint2*)&Vl[((s * 8 + nt) * 32 + lane) * 2];
                }
                #pragma unroll
                for (int j = 0; j < 4; j++) mma16(o[ntb * 4 + j], ph, v_h[j]);
                #pragma unroll
                for (int j = 0; j < 4; j++) mma16(o[ntb * 4 + j], ph, v_l[j]);
                #pragma unroll
                for (int j = 0; j < 4; j++) mma16(o[ntb * 4 + j], pl, v_h[j]);
            }
        }
        __syncthreads();
    }

    // ---- epilogue: write A-fragment hi/lo for the out-projection ----
    float il0 = 1.0f / l0, il1 = 1.0f / l1;
    #pragma unroll
    for (int nt = 0; nt < 8; nt++) {
        int chA = h * 2 + (nt >> 2);
        int sA  = (nt & 3) >> 1;
        uint32_t base = ((uint32_t)(qt * 32 + chA) << 10)
                      + ((sA * 4 + wid) * 32 + lane) * 4 + ((nt & 1) << 1);
        uint32_t hh, ll;
        bsplit(o[nt][0] * il0, o[nt][1] * il0, hh, ll);
        gAh[base] = hh; gAl[base] = ll;
        bsplit(o[nt][2] * il1, o[nt][3] * il1, hh, ll);
        gAh[base + 1] = hh; gAl[base + 1] = ll;
    }
}

// ---------------- launch ----------------------------------------------------
extern "C" void kernel_launch(void* const* d_in, const int* in_sizes, int n_in,
                              void* d_out, int out_size)
{
    const float* X  = (const float*)d_in[0];
    const float* Wq = (const float*)d_in[1];
    const float* Wk = (const float*)d_in[2];
    const float* Wv = (const float*)d_in[3];
    const float* Wo = (const float*)d_in[4];
    float* out = (float*)d_out;

    uint32_t *pXh, *pXl, *pWh, *pWl, *pWoh, *pWol, *pAh, *pAl;
    cudaGetSymbolAddress((void**)&pXh, gXh);
    cudaGetSymbolAddress((void**)&pXl, gXl);
    cudaGetSymbolAddress((void**)&pWh, gWh);
    cudaGetSymbolAddress((void**)&pWl, gWl);
    cudaGetSymbolAddress((void**)&pWoh, gWoh);
    cudaGetSymbolAddress((void**)&pWol, gWol);
    cudaGetSymbolAddress((void**)&pAh, gAh);
    cudaGetSymbolAddress((void**)&pAl, gAl);

    cudaFuncSetAttribute(gemm_frag_kernel,
                         cudaFuncAttributeMaxDynamicSharedMemorySize, GEMM_SMEM);
    cudaFuncSetAttribute(attn_frag_kernel,
                         cudaFuncAttributeMaxDynamicSharedMemorySize, ATT_SMEM);

    // Merged gather-style conversions (coalesced stores)
    convAll_kernel<<<3584, 256>>>(X, Wq, Wk, Wv, Wo);

    // Merged QKV (modes: bx<8 Q+RoPE, bx 8-9 K+RoPE, bx 10-11 V)
    gemm_frag_kernel<<<dim3(12, 16), 256, GEMM_SMEM>>>(pXh, pXl, pWh, pWl, nullptr, 1);

    // Flash attention (reads/writes fragment-ordered globals)
    attn_frag_kernel<<<dim3(32, NH), 128, ATT_SMEM>>>();

    // Output projection (mode 0: plain fp32 store)
    gemm_frag_kernel<<<dim3(8, 16), 256, GEMM_SMEM>>>(pAh, pAl, pWoh, pWol, out, 0);
}

// round 11
// speedup vs baseline: 7.1413x; 1.1090x over previous
#include <cuda_runtime.h>
#include <cuda_bf16.h>
#include <math.h>
#include <stdint.h>

// Problem constants
#define S    2048
#define HID  1024
#define NH   16
#define NKV  4
#define HD   64

// ---------------- fragment-ordered scratch (device globals) -----------------
// A-fragment chunk (64 rows x 32 k, 1024 u32): idx = ((s*4+mt)*32+lane)*4+rg
// B-fragment chunk (128 cols x 32 k, 2048 u32): idx = ((s*16+nt)*32+lane)*2+rg
__device__ uint32_t gXh[32 * 32 * 1024], gXl[32 * 32 * 1024];   // X A-frag
__device__ uint32_t gWh[12 * 32 * 2048], gWl[12 * 32 * 2048];   // Wq|Wk|Wv B-frag
__device__ uint32_t gWoh[8 * 32 * 2048], gWol[8 * 32 * 2048];   // Wo B-frag
__device__ uint32_t gQh[16 * 32 * 2048], gQl[16 * 32 * 2048];   // Q attn A-frag
__device__ uint32_t gKh[4 * 32 * 2048],  gKl[4 * 32 * 2048];    // K attn B-frag
__device__ uint32_t gVh[4 * 32 * 2048],  gVl[4 * 32 * 2048];    // V attn B-frag
__device__ uint32_t gAh[32 * 32 * 1024], gAl[32 * 32 * 1024];   // attn out A-frag

// ---------------- helpers ----------------------------------------------------
__device__ __forceinline__ void bsplit(float x, float y, uint32_t& hi, uint32_t& lo) {
    __nv_bfloat162 h = __floats2bfloat162_rn(x, y);
    float hx = __bfloat162float(h.x);
    float hy = __bfloat162float(h.y);
    __nv_bfloat162 l = __floats2bfloat162_rn(x - hx, y - hy);
    hi = *(uint32_t*)&h;
    lo = *(uint32_t*)&l;
}

__device__ __forceinline__ void mma16(float* d, const uint32_t* a, const uint32_t* b) {
    asm volatile(
        "mma.sync.aligned.m16n8k16.row.col.f32.bf16.bf16.f32 "
        "{%0,%1,%2,%3}, {%4,%5,%6,%7}, {%8,%9}, {%0,%1,%2,%3};"
        : "+f"(d[0]), "+f"(d[1]), "+f"(d[2]), "+f"(d[3])
        : "r"(a[0]), "r"(a[1]), "r"(a[2]), "r"(a[3]), "r"(b[0]), "r"(b[1]));
}

__device__ __forceinline__ void cp16(uint32_t saddr, const void* g) {
    asm volatile("cp.async.cg.shared.global [%0], [%1], 16;" :: "r"(saddr), "l"(g));
}
#define CP_COMMIT asm volatile("cp.async.commit_group;" ::: "memory")
#define CP_WAIT0  asm volatile("cp.async.wait_group 0;" ::: "memory")
#define CP_WAIT1  asm volatile("cp.async.wait_group 1;" ::: "memory")

#define L2T16 (13.287712379549449f / 16.0f)   // log2(10000)/16

// ================= merged gather-style conversion kernel =====================
__global__ __launch_bounds__(256) void convAll_kernel(
    const float* __restrict__ X,
    const float* __restrict__ Wq, const float* __restrict__ Wk,
    const float* __restrict__ Wv, const float* __restrict__ Wo)
{
    const int bx = blockIdx.x;
    const int tid = threadIdx.x;

    if (bx < 1024) {
        int t = bx * 256 + tid;
        int chunkg = t >> 8;
        int fr = t & 255;
        int ln = fr & 31, smt = fr >> 5;
        int s = smt >> 2, mt = smt & 3;
        int mb = chunkg >> 5, ch = chunkg & 31;
        int c = ln & 3, r8 = ln >> 2;
        int rowA = mb * 64 + mt * 16 + r8;
        int kb = ch * 32 + s * 16 + c * 2;

        float2 v0 = *(const float2*)(X + (size_t)rowA * HID + kb);
        float2 v1 = *(const float2*)(X + (size_t)(rowA + 8) * HID + kb);
        float2 v2 = *(const float2*)(X + (size_t)rowA * HID + kb + 8);
        float2 v3 = *(const float2*)(X + (size_t)(rowA + 8) * HID + kb + 8);
        uint4 H, L;
        bsplit(v0.x, v0.y, H.x, L.x);
        bsplit(v1.x, v1.y, H.y, L.y);
        bsplit(v2.x, v2.y, H.z, L.z);
        bsplit(v3.x, v3.y, H.w, L.w);
        *(uint4*)&gXh[((size_t)chunkg << 10) + fr * 4] = H;
        *(uint4*)&gXl[((size_t)chunkg << 10) + fr * 4] = L;
    } else {
        const float* W; uint32_t *Gh, *Gl; int N, nb_base, t;
        if (bx < 2048)      { W = Wq; N = 1024; nb_base = 0;  t = (bx - 1024) * 256 + tid;
                              Gh = gWh;  Gl = gWl; }
        else if (bx < 2304) { W = Wk; N = 256;  nb_base = 8;  t = (bx - 2048) * 256 + tid;
                              Gh = gWh;  Gl = gWl; }
        else if (bx < 2560) { W = Wv; N = 256;  nb_base = 10; t = (bx - 2304) * 256 + tid;
                              Gh = gWh;  Gl = gWl; }
        else                { W = Wo; N = 1024; nb_base = 0;  t = (bx - 2560) * 256 + tid;
                              Gh = gWoh; Gl = gWol; }
        int chunkg = t >> 10;
        int fr = t & 1023;
        int ln = fr & 31, snt = fr >> 5;
        int s = snt >> 4, nt = snt & 15;
        int nb = chunkg >> 5, ch = chunkg & 31;
        int c = ln & 3, nn7 = ln >> 2;
        int n = nb * 128 + nt * 8 + nn7;
        int k0 = ch * 32 + s * 16 + c * 2;
        int k1 = k0 + 8;

        float a0 = W[(size_t)k0 * N + n];
        float a1 = W[(size_t)(k0 + 1) * N + n];
        float b0 = W[(size_t)k1 * N + n];
        float b1 = W[(size_t)(k1 + 1) * N + n];
        uint2 H, L;
        bsplit(a0, a1, H.x, L.x);
        bsplit(b0, b1, H.y, L.y);
        size_t base = ((size_t)((nb_base + nb) * 32 + ch) << 11) + fr * 2;
        *(uint2*)&Gh[base] = H;
        *(uint2*)&Gl[base] = L;
    }
}

// ================= fragment GEMM (3xBF16, 3-stage, 1 barrier/chunk) ==========
// Block: 64(M) x 128(N), BK=32, 128 threads (4 warps: 2 M x 2 N).
// 3 smem stages x (Ah 1024 | Al 1024 | Bh 2048 | Bl 2048) u32 = 72 KB.
#define GEMM_SMEM (3 * 6144 * 4)

__global__ __launch_bounds__(128, 3) void gemm_frag_kernel(
    const uint32_t* __restrict__ Agh, const uint32_t* __restrict__ Agl,
    const uint32_t* __restrict__ Wgh, const uint32_t* __restrict__ Wgl,
    float* __restrict__ Cout, int qkv)
{
    extern __shared__ uint32_t sm[];
    const uint32_t sb = (uint32_t)__cvta_generic_to_shared(sm);
    const int tid  = threadIdx.x;
    const int wid  = tid >> 5;
    const int lane = tid & 31;
    const int wm   = wid & 1;
    const int wn   = wid >> 1;
    const int mb   = blockIdx.y;
    const int bx   = blockIdx.x;
    const int m0   = mb * 64;

    const uint32_t* Ah_src = Agh + ((size_t)mb << 15);
    const uint32_t* Al_src = Agl + ((size_t)mb << 15);
    const uint32_t* Bh_src = Wgh + ((size_t)bx << 16);
    const uint32_t* Bl_src = Wgl + ((size_t)bx << 16);

    float acc[2][8][4];
    #pragma unroll
    for (int i = 0; i < 2; i++)
        #pragma unroll
        for (int j = 0; j < 8; j++)
            #pragma unroll
            for (int v = 0; v < 4; v++) acc[i][j][v] = 0.f;

    auto issue = [&](int ch, int buf) {
        uint32_t db = sb + buf * 6144 * 4;
        #pragma unroll
        for (int i = 0; i < 2; i++) {
            int j = tid + i * 128;
            cp16(db + j * 16,             Ah_src + (ch << 10) + j * 4);
            cp16(db + 4096 + j * 16,      Al_src + (ch << 10) + j * 4);
        }
        #pragma unroll
        for (int i = 0; i < 4; i++) {
            int j = tid + i * 128;
            cp16(db + 8192 + j * 16,      Bh_src + (ch << 11) + j * 4);
            cp16(db + 16384 + j * 16,     Bl_src + (ch << 11) + j * 4);
        }
    };
    auto compute = [&](int buf) {
        const uint32_t* Ah = sm + buf * 6144;
        const uint32_t* Al = Ah + 1024;
        const uint32_t* Bh = Ah + 2048;
        const uint32_t* Bl = Ah + 4096;
        #pragma unroll
        for (int s = 0; s < 2; s++) {
            uint32_t a_h[2][4], a_l[2][4];
            #pragma unroll
            for (int mt = 0; mt < 2; mt++) {
                *(uint4*)a_h[mt] = *(const uint4*)&Ah[((s * 4 + wm * 2 + mt) * 32 + lane) * 4];
                *(uint4*)a_l[mt] = *(const uint4*)&Al[((s * 4 + wm * 2 + mt) * 32 + lane) * 4];
            }
            #pragma unroll
            for (int ntb = 0; ntb < 2; ntb++) {
                uint32_t b_h[4][2], b_l[4][2];
                #pragma unroll
                for (int j = 0; j < 4; j++) {
                    int nt = wn * 8 + ntb * 4 + j;
                    *(uint2*)b_h[j] = *(const uint2*)&Bh[((s * 16 + nt) * 32 + lane) * 2];
                    *(uint2*)b_l[j] = *(const uint2*)&Bl[((s * 16 + nt) * 32 + lane) * 2];
                }
                #pragma unroll
                for (int j = 0; j < 4; j++)
                    #pragma unroll
                    for (int mt = 0; mt < 2; mt++) {
                        mma16(acc[mt][ntb * 4 + j], a_h[mt], b_h[j]);
                        mma16(acc[mt][ntb * 4 + j], a_h[mt], b_l[j]);
                        mma16(acc[mt][ntb * 4 + j], a_l[mt], b_h[j]);
                    }
            }
        }
    };

    // 3-stage pipeline, ONE barrier per chunk.
    issue(0, 0); CP_COMMIT;
    issue(1, 1); CP_COMMIT;
    for (int ch = 0; ch < 32; ch++) {
        if (ch < 31) { CP_WAIT1; } else { CP_WAIT0; }
        __syncthreads();            // chunk ch visible; all warps done with ch-1
        compute(ch % 3);
        if (ch + 2 < 32) { issue(ch + 2, (ch + 2) % 3); CP_COMMIT; }
    }

    // ---- epilogue ----
    const int mode = qkv ? (bx < 8 ? 1 : (bx < 10 ? 2 : 3)) : 0;

    #pragma unroll
    for (int mt = 0; mt < 2; mt++) {
        const int tile16 = wm * 2 + mt;
        const int row = m0 + tile16 * 16 + (lane >> 2);
        #pragma unroll
        for (int nt = 0; nt < 8; nt++) {
            const int nglob = wn * 8 + nt;
            const int nn = nglob & 7;
            float v0 = acc[mt][nt][0], v1 = acc[mt][nt][1];
            float v2 = acc[mt][nt][2], v3 = acc[mt][nt][3];

            if (mode == 0) {
                int col = bx * 128 + nglob * 8 + (lane & 3) * 2;
                *(float2*)(Cout + (size_t)row * HID + col) = make_float2(v0, v1);
                *(float2*)(Cout + (size_t)(row + 8) * HID + col) = make_float2(v2, v3);
            } else if (mode == 1) {          // Q: RoPE + 1/8 -> attn A-frag
                int h2 = bx * 2 + (nglob >> 3);
                int fidx = (nn * 4 + (lane & 3)) & 15;
                float inv = exp2f(-(float)fidx * L2T16);
                uint32_t base = ((uint32_t)(h2 * 32 + mb) << 11)
                              + ((tile16 * 4 + (nn >> 1)) * 32 + lane) * 4
                              + ((nn & 1) << 1);
                float sn, cs;
                sincosf((float)row * inv, &sn, &cs);
                uint32_t hh, ll;
                bsplit((v0 * cs - v1 * sn) * 0.125f, (v0 * sn + v1 * cs) * 0.125f, hh, ll);
                gQh[base] = hh; gQl[base] = ll;
                sincosf((float)(row + 8) * inv, &sn, &cs);
                bsplit((v2 * cs - v3 * sn) * 0.125f, (v2 * sn + v3 * cs) * 0.125f, hh, ll);
                gQh[base + 1] = hh; gQl[base + 1] = ll;
            } else if (mode == 2) {          // K: RoPE -> attn B-frag
                int kvh2 = (bx - 8) * 2 + (nglob >> 3);
                int fidx = (nn * 4 + (lane & 3)) & 15;
                float inv = exp2f(-(float)fidx * L2T16);
                uint32_t kb = (uint32_t)(kvh2 * 32 + mb) << 11;
                int sK = nn >> 1;
                int kt8 = tile16 * 2;
                float sn, cs;
                sincosf((float)row * inv, &sn, &cs);
                uint32_t hh, ll;
                bsplit(v0 * cs - v1 * sn, v0 * sn + v1 * cs, hh, ll);
                uint32_t i0 = kb + (((sK * 8 + kt8) * 32 + lane) << 1) + (nn & 1);
                gKh[i0] = hh; gKl[i0] = ll;
                sincosf((float)(row + 8) * inv, &sn, &cs);
                bsplit(v2 * cs - v3 * sn, v2 * sn + v3 * cs, hh, ll);
                uint32_t i1 = kb + (((sK * 8 + kt8 + 1) * 32 + lane) << 1) + (nn & 1);
                gKh[i1] = hh; gKl[i1] = ll;
            } else {                         // V: pair rows via shfl -> attn B-frag
                int kvh2 = (bx - 10) * 2 + (nglob >> 3);
                float b0 = __shfl_xor_sync(0xffffffffu, v0, 4);
                float b1 = __shfl_xor_sync(0xffffffffu, v1, 4);
                float b2 = __shfl_xor_sync(0xffffffffu, v2, 4);
                float b3 = __shfl_xor_sync(0xffffffffu, v3, 4);
                if (!(lane & 4)) {
                    uint32_t vb = (uint32_t)(kvh2 * 32 + mb) << 11;
                    #pragma unroll
                    for (int grp = 0; grp < 2; grp++) {
                        int kp = tile16 * 8 + grp * 4 + (lane >> 3);
                        int sv = kp >> 3, cv = kp & 3, rgv = (kp >> 2) & 1;
                        #pragma unroll
                        for (int colsel = 0; colsel < 2; colsel++) {
                            float x0 = grp ? (colsel ? v3 : v2) : (colsel ? v1 : v0);
                            float x1 = grp ? (colsel ? b3 : b2) : (colsel ? b1 : b0);
                            int d7 = (lane & 3) * 2 + colsel;
                            uint32_t idx = vb + ((((sv * 8 + nn) << 5)
                                         + ((d7 << 2) | cv)) << 1) + rgv;
                            uint32_t hh, ll;
                            bsplit(x0, x1, hh, ll);
                            gVh[idx] = hh; gVl[idx] = ll;
                        }
                    }
                }
            }
        }
    }
}

// ================= MMA flash attention (bf16 3x, causal, GQA 4:1) ============
#define ATT_SMEM (2 * 8192 * 4)

__global__ __launch_bounds__(128, 3) void attn_frag_kernel()
{
    extern __shared__ uint32_t sm[];
    const uint32_t sb = (uint32_t)__cvta_generic_to_shared(sm);
    const int tid  = threadIdx.x;
    const int wid  = tid >> 5;
    const int lane = tid & 31;

    const int h   = blockIdx.y;
    const int qt  = gridDim.x - 1 - blockIdx.x;   // heavy tiles first
    const int q0  = qt * 64;
    const int kvh = h >> 2;

    uint32_t qh[4][4], ql[4][4];
    {
        const uint32_t* Qb = gQh + ((size_t)(h * 32 + qt) << 11);
        const uint32_t* Qb2 = gQl + ((size_t)(h * 32 + qt) << 11);
        #pragma unroll
        for (int s = 0; s < 4; s++) {
            *(uint4*)qh[s] = *(const uint4*)&Qb[((wid * 4 + s) * 32 + lane) * 4];
            *(uint4*)ql[s] = *(const uint4*)&Qb2[((wid * 4 + s) * 32 + lane) * 4];
        }
    }

    const int r0 = q0 + wid * 16 + (lane >> 2);
    const int r1 = r0 + 8;
    const int c2 = (lane & 3) * 2;

    float m0 = -1e30f, m1 = -1e30f, l0 = 0.f, l1 = 0.f;
    float o[8][4];
    #pragma unroll
    for (int nt = 0; nt < 8; nt++)
        #pragma unroll
        for (int v = 0; v < 4; v++) o[nt][v] = 0.f;

    auto issue = [&](int t, int buf) {
        uint32_t db = sb + buf * 8192 * 4;
        const uint32_t* kh = gKh + ((size_t)(kvh * 32 + t) << 11);
        const uint32_t* kl = gKl + ((size_t)(kvh * 32 + t) << 11);
        const uint32_t* vh = gVh + ((size_t)(kvh * 32 + t) << 11);
        const uint32_t* vl = gVl + ((size_t)(kvh * 32 + t) << 11);
        #pragma unroll
        for (int i = 0; i < 4; i++) {
            int j = tid + i * 128;
            cp16(db + j * 16,          kh + j * 4);
            cp16(db + 8192 + j * 16,   kl + j * 4);
            cp16(db + 16384 + j * 16,  vh + j * 4);
            cp16(db + 24576 + j * 16,  vl + j * 4);
        }
    };

    issue(0, 0); CP_COMMIT;
    for (int t = 0; t <= qt; t++) {
        if (t < qt) { issue(t + 1, (t + 1) & 1); CP_COMMIT; }
        if (t < qt) { CP_WAIT1; } else { CP_WAIT0; }
        __syncthreads();

        const uint32_t* Kh = sm + (t & 1) * 8192;
        const uint32_t* Kl = Kh + 2048;
        const uint32_t* Vh = Kh + 4096;
        const uint32_t* Vl = Kh + 6144;
        const int kv0 = t * 64;

        float s_[8][4];
        #pragma unroll
        for (int nt = 0; nt < 8; nt++)
            #pragma unroll
            for (int v = 0; v < 4; v++) s_[nt][v] = 0.f;
        #pragma unroll
        for (int s = 0; s < 4; s++) {
            #pragma unroll
            for (int ntb = 0; ntb < 2; ntb++) {
                uint32_t k_h[4][2], k_l[4][2];
                #pragma unroll
                for (int j = 0; j < 4; j++) {
                    int nt = ntb * 4 + j;
                    *(uint2*)k_h[j] = *(const uint2*)&Kh[((s * 8 + nt) * 32 + lane) * 2];
                    *(uint2*)k_l[j] = *(const uint2*)&Kl[((s * 8 + nt) * 32 + lane) * 2];
                }
                #pragma unroll
                for (int j = 0; j < 4; j++) mma16(s_[ntb * 4 + j], qh[s], k_h[j]);
                #pragma unroll
                for (int j = 0; j < 4; j++) mma16(s_[ntb * 4 + j], qh[s], k_l[j]);
                #pragma unroll
                for (int j = 0; j < 4; j++) mma16(s_[ntb * 4 + j], ql[s], k_h[j]);
            }
        }

        if (t == qt) {
            #pragma unroll
            for (int nt = 0; nt < 8; nt++) {
                int cb = kv0 + nt * 8 + c2;
                if (cb > r0)     s_[nt][0] = -1e30f;
                if (cb + 1 > r0) s_[nt][1] = -1e30f;
                if (cb > r1)     s_[nt][2] = -1e30f;
                if (cb + 1 > r1) s_[nt][3] = -1e30f;
            }
        }

        float tm0 = -1e30f, tm1 = -1e30f;
        #pragma unroll
        for (int nt = 0; nt < 8; nt++) {
            tm0 = fmaxf(tm0, fmaxf(s_[nt][0], s_[nt][1]));
            tm1 = fmaxf(tm1, fmaxf(s_[nt][2], s_[nt][3]));
        }
        tm0 = fmaxf(tm0, __shfl_xor_sync(0xffffffffu, tm0, 1));
        tm0 = fmaxf(tm0, __shfl_xor_sync(0xffffffffu, tm0, 2));
        tm1 = fmaxf(tm1, __shfl_xor_sync(0xffffffffu, tm1, 1));
        tm1 = fmaxf(tm1, __shfl_xor_sync(0xffffffffu, tm1, 2));
        float mn0 = fmaxf(m0, tm0), mn1 = fmaxf(m1, tm1);
        float f0 = __expf(m0 - mn0), f1 = __expf(m1 - mn1);
        m0 = mn0; m1 = mn1;
        float rs0 = 0.f, rs1 = 0.f;
        #pragma unroll
        for (int nt = 0; nt < 8; nt++) {
            s_[nt][0] = __expf(s_[nt][0] - mn0); rs0 += s_[nt][0];
            s_[nt][1] = __expf(s_[nt][1] - mn0); rs0 += s_[nt][1];
            s_[nt][2] = __expf(s_[nt][2] - mn1); rs1 += s_[nt][2];
            s_[nt][3] = __expf(s_[nt][3] - mn1); rs1 += s_[nt][3];
        }
        rs0 += __shfl_xor_sync(0xffffffffu, rs0, 1);
        rs0 += __shfl_xor_sync(0xffffffffu, rs0, 2);
        rs1 += __shfl_xor_sync(0xffffffffu, rs1, 1);
        rs1 += __shfl_xor_sync(0xffffffffu, rs1, 2);
        l0 = l0 * f0 + rs0;
        l1 = l1 * f1 + rs1;
        #pragma unroll
        for (int nt = 0; nt < 8; nt++) {
            o[nt][0] *= f0; o[nt][1] *= f0;
            o[nt][2] *= f1; o[nt][3] *= f1;
        }

        #pragma unroll
        for (int s = 0; s < 4; s++) {
            uint32_t ph[4], pl[4];
            bsplit(s_[2 * s][0],     s_[2 * s][1],     ph[0], pl[0]);
            bsplit(s_[2 * s][2],     s_[2 * s][3],     ph[1], pl[1]);
            bsplit(s_[2 * s + 1][0], s_[2 * s + 1][1], ph[2], pl[2]);
            bsplit(s_[2 * s + 1][2], s_[2 * s + 1][3], ph[3], pl[3]);
            #pragma unroll
            for (int ntb = 0; ntb < 2; ntb++) {
                uint32_t v_h[4][2], v_l[4][2];
                #pragma unroll
                for (int j = 0; j < 4; j++) {
                    int nt = ntb * 4 + j;
                    *(uint2*)v_h[j] = *(const uint2*)&Vh[((s * 8 + nt) * 32 + lane) * 2];
                    *(uint2*)v_l[j] = *(const uint2*)&Vl[((s * 8 + nt) * 32 + lane) * 2];
                }
                #pragma unroll
                for (int j = 0; j < 4; j++) mma16(o[ntb * 4 + j], ph, v_h[j]);
                #pragma unroll
                for (int j = 0; j < 4; j++) mma16(o[ntb * 4 + j], ph, v_l[j]);
                #pragma unroll
                for (int j = 0; j < 4; j++) mma16(o[ntb * 4 + j], pl, v_h[j]);
            }
        }
        __syncthreads();
    }

    // ---- epilogue: write A-fragment hi/lo for the out-projection ----
    float il0 = 1.0f / l0, il1 = 1.0f / l1;
    #pragma unroll
    for (int nt = 0; nt < 8; nt++) {
        int chA = h * 2 + (nt >> 2);
        int sA  = (nt & 3) >> 1;
        uint32_t base = ((uint32_t)(qt * 32 + chA) << 10)
                      + ((sA * 4 + wid) * 32 + lane) * 4 + ((nt & 1) << 1);
        uint32_t hh, ll;
        bsplit(o[nt][0] * il0, o[nt][1] * il0, hh, ll);
        gAh[base] = hh; gAl[base] = ll;
        bsplit(o[nt][2] * il1, o[nt][3] * il1, hh, ll);
        gAh[base + 1] = hh; gAl[base + 1] = ll;
    }
}

// ---------------- launch ----------------------------------------------------
extern "C" void kernel_launch(void* const* d_in, const int* in_sizes, int n_in,
                              void* d_out, int out_size)
{
    const float* X  = (const float*)d_in[0];
    const float* Wq = (const float*)d_in[1];
    const float* Wk = (const float*)d_in[2];
    const float* Wv = (const float*)d_in[3];
    const float* Wo = (const float*)d_in[4];
    float* out = (float*)d_out;

    uint32_t *pXh, *pXl, *pWh, *pWl, *pWoh, *pWol, *pAh, *pAl;
    cudaGetSymbolAddress((void**)&pXh, gXh);
    cudaGetSymbolAddress((void**)&pXl, gXl);
    cudaGetSymbolAddress((void**)&pWh, gWh);
    cudaGetSymbolAddress((void**)&pWl, gWl);
    cudaGetSymbolAddress((void**)&pWoh, gWoh);
    cudaGetSymbolAddress((void**)&pWol, gWol);
    cudaGetSymbolAddress((void**)&pAh, gAh);
    cudaGetSymbolAddress((void**)&pAl, gAl);

    cudaFuncSetAttribute(gemm_frag_kernel,
                         cudaFuncAttributeMaxDynamicSharedMemorySize, GEMM_SMEM);
    cudaFuncSetAttribute(attn_frag_kernel,
                         cudaFuncAttributeMaxDynamicSharedMemorySize, ATT_SMEM);

    // Merged gather-style conversions (coalesced stores)
    convAll_kernel<<<3584, 256>>>(X, Wq, Wk, Wv, Wo);

    // Merged QKV (modes: bx<8 Q+RoPE, bx 8-9 K+RoPE, bx 10-11 V)
    gemm_frag_kernel<<<dim3(12, 32), 128, GEMM_SMEM>>>(pXh, pXl, pWh, pWl, nullptr, 1);

    // Flash attention (reads/writes fragment-ordered globals)
    attn_frag_kernel<<<dim3(32, NH), 128, ATT_SMEM>>>();

    // Output projection (mode 0: plain fp32 store)
    gemm_frag_kernel<<<dim3(8, 32), 128, GEMM_SMEM>>>(pAh, pAl, pWoh, pWol, out, 0);
}